// round 10
// baseline (speedup 1.0000x reference)
#include <cuda_runtime.h>
#include <cuda_bf16.h>
#include <math.h>
#include <stdint.h>

#define NH 12
#define NB 16
#define NS 512
#define ND 768
#define NF 3072
#define NL 4
#define NDH 64
#define MROWS (NB*NS)      // 8192
#define NBH (NB*NH)        // 192

typedef __nv_bfloat16 bf16;

#if defined(__CUDA_ARCH_FEAT_SM103_ALL)
#define HAS_TC 1
#else
#define HAS_TC 0
#endif

// ---------------- scratch ----------------
__device__ float g_xf[MROWS*ND];
__device__ float g_tmp[MROWS*ND];
__device__ float g_attnf[MROWS*ND];
__device__ float g_s1[(size_t)NBH*NS*NS];
__device__ float g_s2[(size_t)NBH*NS*NS];
__device__ float g_cninv[NBH*NS];
__device__ float g_st1[(size_t)NBH*2*NS*2];
__device__ float g_st2[(size_t)NBH*2*NS*2];
__device__ float g_smc[(size_t)NBH*NS*4];

__device__ bf16 g_xh[MROWS*ND],   g_xl[MROWS*ND];
__device__ bf16 g_prjh[(size_t)MROWS*4*ND], g_prjl[(size_t)MROWS*4*ND]; // q|k|c|v
__device__ bf16 g_ctxh[MROWS*ND], g_ctxl[MROWS*ND];
__device__ bf16 g_ath[MROWS*ND],  g_atl[MROWS*ND];
__device__ bf16 g_hh[(size_t)MROWS*NF], g_hl[(size_t)MROWS*NF];
__device__ bf16 g_vth[NBH*NDH*NS], g_vtl[NBH*NDH*NS];

#define WDD (768*768)
#define WDF (768*3072)
#define CATW (4*WDD)
__device__ bf16 g_wcath[NL*CATW], g_wcatl[NL*CATW];
__device__ bf16 g_woh[NL*WDD], g_wol[NL*WDD];
__device__ bf16 g_wih[NL*WDF], g_wil[NL*WDF];
__device__ bf16 g_wo2h[NL*WDF], g_wo2l[NL*WDF];
__device__ float g_bcat[NL*4*ND];

// ---------------- helpers ----------------
__device__ __forceinline__ void split2(float v, bf16& h, bf16& l) {
    h = __float2bfloat16(v);
    l = __float2bfloat16(v - __bfloat162float(h));
}

__device__ __forceinline__ void cpa16(uint32_t dst, const void* src, int sz) {
    asm volatile("cp.async.cg.shared.global [%0], [%1], 16, %2;" :: "r"(dst), "l"(src), "r"(sz));
}

#define FENCE_PROXY_ASYNC() \
    asm volatile("fence.proxy.async.shared::cta;" ::: "memory")

#define STS128X(r0,r1,r2,r3,addr) \
    asm volatile("st.shared.v4.b32 [%0], {%1,%2,%3,%4};" \
        :: "r"(addr), "r"(r0), "r"(r1), "r"(r2), "r"(r3) : "memory")

#if HAS_TC
__device__ __forceinline__ uint32_t elect_one_pred() {
    uint32_t pred;
    asm volatile(
        "{\n\t.reg .pred p;\n\t"
        "elect.sync _|p, 0xFFFFFFFF;\n\t"
        "selp.b32 %0, 1, 0, p;\n\t}"
        : "=r"(pred));
    return pred;
}

static constexpr uint64_t SMEM_DESC_BASE_SW128 =
    (uint64_t(2) << 61) | (uint64_t(1) << 46) | (uint64_t(64) << 32) | (uint64_t(1) << 16);
#define MAKE_SMEM_DESC(base_addr) \
    (SMEM_DESC_BASE_SW128 | ((uint64_t)((base_addr) >> 4) & 0x3FFF))

#define TCGEN05_ALLOC(smem_result_addr, nCols) \
    asm volatile("tcgen05.alloc.cta_group::1.sync.aligned.shared::cta.b32 [%0], %1;" \
        :: "r"((uint32_t)(smem_result_addr)), "r"((uint32_t)(nCols)) : "memory")
#define TCGEN05_DEALLOC(tmem_addr, nCols) \
    asm volatile("tcgen05.dealloc.cta_group::1.sync.aligned.b32 %0, %1;" \
        :: "r"(tmem_addr), "r"((uint32_t)(nCols)))
#define TCGEN05_RELINQ() \
    asm volatile("tcgen05.relinquish_alloc_permit.cta_group::1.sync.aligned;")
#define TCGEN05_COMMIT(mbar) \
    asm volatile("tcgen05.commit.cta_group::1.mbarrier::arrive::one.shared::cluster.b64 [%0];" \
        :: "r"((uint32_t)(mbar)) : "memory")
#define TCGEN05_WAIT_LD() \
    asm volatile("tcgen05.wait::ld.sync.aligned;" ::: "memory")
#define TCGEN05_FENCE_AFTER() \
    asm volatile("tcgen05.fence::after_thread_sync;" ::: "memory")
#define TCGEN05_FENCE_BEFORE() \
    asm volatile("tcgen05.fence::before_thread_sync;" ::: "memory")

#define MBARRIER_INIT(mbar, count) \
    asm volatile("mbarrier.init.shared.b64 [%0], %1;" \
        :: "r"((uint32_t)(mbar)), "r"((uint32_t)(count)) : "memory")
#define MBARRIER_INVAL(mbar) \
    asm volatile("mbarrier.inval.shared.b64 [%0];" :: "r"((uint32_t)(mbar)) : "memory")
#define MBARRIER_WAIT_PARITY(mbar_addr, phase_parity) do { \
    uint32_t _mbar = (uint32_t)(mbar_addr); \
    uint32_t _parity = (uint32_t)(phase_parity); \
    uint32_t _done; \
    asm volatile( \
        "{\n\t.reg .pred p;\n\t" \
        "mbarrier.try_wait.parity.acquire.cta.shared::cta.b64 p, [%1], %2;\n\t" \
        "selp.b32 %0, 1, 0, p;\n\t}" \
        : "=r"(_done) : "r"(_mbar), "r"(_parity) : "memory"); \
    if (!_done) { \
        asm volatile( \
            "{\n\t.reg .pred P1;\n\t" \
            "WAIT_LOOP_%=:\n\t" \
            "mbarrier.try_wait.parity.acquire.cta.shared::cta.b64 P1, [%0], %1, 0x989680;\n\t" \
            "@P1 bra.uni WAIT_DONE_%=;\n\t" \
            "bra.uni WAIT_LOOP_%=;\n\t" \
            "WAIT_DONE_%=:\n\t}" \
            :: "r"(_mbar), "r"(_parity) : "memory"); \
    } \
} while(0)

#define TCGEN05_LD_32X32B_X32(r, tmem_addr) \
    asm volatile( \
        "tcgen05.ld.sync.aligned.32x32b.x32.b32 " \
        "{%0, %1, %2, %3, %4, %5, %6, %7, " \
        " %8, %9, %10, %11, %12, %13, %14, %15, " \
        " %16, %17, %18, %19, %20, %21, %22, %23, " \
        " %24, %25, %26, %27, %28, %29, %30, %31}, [%32];" \
        : "=r"((r)[0]),  "=r"((r)[1]),  "=r"((r)[2]),  "=r"((r)[3]), \
          "=r"((r)[4]),  "=r"((r)[5]),  "=r"((r)[6]),  "=r"((r)[7]), \
          "=r"((r)[8]),  "=r"((r)[9]),  "=r"((r)[10]), "=r"((r)[11]), \
          "=r"((r)[12]), "=r"((r)[13]), "=r"((r)[14]), "=r"((r)[15]), \
          "=r"((r)[16]), "=r"((r)[17]), "=r"((r)[18]), "=r"((r)[19]), \
          "=r"((r)[20]), "=r"((r)[21]), "=r"((r)[22]), "=r"((r)[23]), \
          "=r"((r)[24]), "=r"((r)[25]), "=r"((r)[26]), "=r"((r)[27]), \
          "=r"((r)[28]), "=r"((r)[29]), "=r"((r)[30]), "=r"((r)[31]) \
        : "r"(tmem_addr))

__device__ __forceinline__ void mma_f16_ss(uint32_t d, uint64_t ad, uint64_t bd,
                                           uint32_t idesc, uint32_t en) {
    asm volatile(
        "{\n\t.reg .pred p;\n\t"
        "setp.ne.u32 p, %5, 0;\n\t"
        "tcgen05.mma.cta_group::1.kind::f16 [%0], %1, %2, %3, {%4, %4, %4, %4}, p;\n\t}"
        :: "r"(d), "l"(ad), "l"(bd), "r"(idesc), "r"(0u), "r"(en) : "memory");
}
#endif

// ---------------- bf16x3 NT GEMM (R8 engine, 128 x TN) ----------------
// EPI: 1 f32+bias, 2 pair+bias, 4 pair+bias+gelu,
//      5 f32 cosine-transform + row stats, 6 f32 *0.125 + row stats
template<int EPI, int TN>
__global__ void __launch_bounds__(256) gemm_tc(
    const bf16* __restrict__ Ah_, const bf16* __restrict__ Al_,
    int lda, long long sAb, long long sAh,
    const bf16* __restrict__ Bh_, const bf16* __restrict__ Bl_,
    int ldb, long long sBb, long long sBh,
    float* __restrict__ Cf, bf16* __restrict__ Coh, bf16* __restrict__ Col,
    int ldc, long long sCb, long long sCh,
    const float* __restrict__ bias,
    int N, int K, int Hdiv, uint32_t idesc,
    const float* __restrict__ cnp, float* __restrict__ statsp)
{
    constexpr int STAGE = (128 + TN) * 256;
    constexpr int AHOF = 0, ALOF = 16384, BHOF = 32768, BLOF = 32768 + TN * 128;
    extern __shared__ __align__(1024) char dsm[];
    const int tid = threadIdx.x, lane = tid & 31, wid = tid >> 5;
    const int zb = blockIdx.z / Hdiv, zh = blockIdx.z % Hdiv;
    const int m0 = blockIdx.y * 128, n0 = blockIdx.x * TN;
    const int nB = min(TN, N - n0);

    const bf16* Agh = Ah_ + zb*sAb + zh*sAh + (long long)m0 * lda;
    const bf16* Agl = Al_ + zb*sAb + zh*sAh + (long long)m0 * lda;
    const bf16* Bgh = Bh_ + zb*sBb + zh*sBh + (long long)n0 * ldb;
    const bf16* Bgl = Bl_ + zb*sBb + zh*sBh + (long long)n0 * ldb;

    float* Cfp = Cf  ? Cf  + zb*sCb + zh*sCh : nullptr;
    bf16*  Chp = Coh ? Coh + zb*sCb + zh*sCh : nullptr;
    bf16*  Clp = Col ? Col + zb*sCb + zh*sCh : nullptr;

#if HAS_TC
    const int nst = (K > 64) ? 2 : 1;
    uint32_t sb  = (uint32_t)__cvta_generic_to_shared(dsm);
    uint32_t ctl = sb + (uint32_t)(nst * STAGE);
    uint32_t mb0 = ctl + 8, mb1 = ctl + 16;

    if (tid == 0) { MBARRIER_INIT(mb0, 1); MBARRIER_INIT(mb1, 1); }
    if (wid == 4) { TCGEN05_ALLOC(ctl, TN); TCGEN05_RELINQ(); }
    __syncthreads();
    uint32_t tmem;
    asm volatile("ld.shared.b32 %0, [%1];" : "=r"(tmem) : "r"(ctl));

    const int KT = K >> 6;
    int ph0 = 0, ph1 = 0;

    auto issue = [&](int buf, int k0) {
        const uint32_t sbase = sb + (uint32_t)(buf * STAGE);
        constexpr int ITER = (128 + TN) * 8 / 256;
        #pragma unroll
        for (int i = 0; i < ITER; i++) {
            int id = tid + (i << 8);
            int row = id >> 3, cc = id & 7;
            if (row < 128) {
                uint32_t off = (uint32_t)((row << 7) + (cc << 4));
                uint32_t sw = off ^ ((off >> 3) & 0x70);
                long long ga = (long long)row * lda + k0 + (cc << 3);
                cpa16(sbase + AHOF + sw, Agh + ga, 16);
                cpa16(sbase + ALOF + sw, Agl + ga, 16);
            } else {
                int rb = row - 128;
                uint32_t off = (uint32_t)((rb << 7) + (cc << 4));
                uint32_t sw = off ^ ((off >> 3) & 0x70);
                int sz = 16, br = rb;
                if (rb >= nB) { sz = 0; br = 0; }
                long long gb = (long long)br * ldb + k0 + (cc << 3);
                cpa16(sbase + BHOF + sw, Bgh + gb, sz);
                cpa16(sbase + BLOF + sw, Bgl + gb, sz);
            }
        }
        asm volatile("cp.async.commit_group;");
    };

    issue(0, 0);
    for (int kt = 0; kt < KT; kt++) {
        const int buf = (nst == 2) ? (kt & 1) : 0;
        if (kt + 1 < KT) {
            if (kt >= 1) {
                if ((buf ^ 1) == 0) { MBARRIER_WAIT_PARITY(mb0, ph0); ph0 ^= 1; }
                else                { MBARRIER_WAIT_PARITY(mb1, ph1); ph1 ^= 1; }
            }
            issue(buf ^ 1, (kt + 1) << 6);
            asm volatile("cp.async.wait_group 1;");
        } else {
            asm volatile("cp.async.wait_group 0;");
        }
        FENCE_PROXY_ASYNC();
        __syncthreads();

        const uint32_t sbase = sb + (uint32_t)(buf * STAGE);
        if (wid == 4) {
            if (elect_one_pred()) {
                uint64_t dah = MAKE_SMEM_DESC(sbase + AHOF);
                uint64_t dal = MAKE_SMEM_DESC(sbase + ALOF);
                uint64_t dbh = MAKE_SMEM_DESC(sbase + BHOF);
                uint64_t dbl = MAKE_SMEM_DESC(sbase + BLOF);
                #pragma unroll
                for (int s = 0; s < 4; s++) {
                    uint32_t en0 = (kt == 0 && s == 0) ? 0u : 1u;
                    mma_f16_ss(tmem, dah + s*2, dbh + s*2, idesc, en0);
                    mma_f16_ss(tmem, dah + s*2, dbl + s*2, idesc, 1u);
                    mma_f16_ss(tmem, dal + s*2, dbh + s*2, idesc, 1u);
                }
                TCGEN05_COMMIT(buf ? mb1 : mb0);
            }
        }
        __syncthreads();
    }

    const int lastbuf = (nst == 2) ? ((KT - 1) & 1) : 0;
    if (lastbuf == 0) { MBARRIER_WAIT_PARITY(mb0, ph0); }
    else              { MBARRIER_WAIT_PARITY(mb1, ph1); }
    TCGEN05_FENCE_AFTER();

    // online row stats for EPI 5/6
    float stm[4], stq[4];
    if (EPI == 5 || EPI == 6) {
        #pragma unroll
        for (int it = 0; it < 4; it++) { stm[it] = -1e30f; stq[it] = 0.f; }
    }

    // epilogue: TMEM -> SMEM pivot -> coalesced stores (R5/R8 proven)
    float* stg = (float*)dsm;
    for (int cb = 0; cb < nB; cb += 32) {
        if (wid < 4) {
            uint32_t d[32];
            TCGEN05_LD_32X32B_X32(d, tmem + cb);
            TCGEN05_WAIT_LD();
            int row = (wid << 5) + lane;
            #pragma unroll
            for (int j = 0; j < 32; j++) stg[row * 33 + j] = __uint_as_float(d[j]);
        }
        __syncthreads();
        #pragma unroll
        for (int it = 0; it < 4; it++) {
            int row = (it << 5) + (tid >> 3);
            int cc = (tid & 7) << 2;
            int gc = n0 + cb + cc;
            long long o = (long long)(m0 + row) * ldc + gc;
            float v[4];
            #pragma unroll
            for (int j = 0; j < 4; j++) {
                v[j] = stg[row * 33 + cc + j];
                if (EPI == 1 || EPI == 2 || EPI == 4) v[j] += bias[gc + j];
                if (EPI == 4) v[j] = 0.5f * v[j] * (1.0f + erff(v[j] * 0.70710678118654752f));
            }
            if (EPI == 5) {
                const float cl = cnp[(long long)blockIdx.z * 512 + m0 + row];
                #pragma unroll
                for (int j = 0; j < 4; j++)
                    v[j] = 1.0f - v[j] * cl * cnp[(long long)blockIdx.z * 512 + gc + j]
                           + ((m0 + row) == (gc + j) ? 1.0f : 0.0f);
            }
            if (EPI == 6) {
                #pragma unroll
                for (int j = 0; j < 4; j++) v[j] *= 0.125f;
            }
            if (EPI == 5 || EPI == 6) {
                float vm = fmaxf(fmaxf(v[0], v[1]), fmaxf(v[2], v[3]));
                float se = __expf(v[0]-vm) + __expf(v[1]-vm) + __expf(v[2]-vm) + __expf(v[3]-vm);
                float nm = fmaxf(stm[it], vm);
                stq[it] = stq[it] * __expf(stm[it] - nm) + se * __expf(vm - nm);
                stm[it] = nm;
            }
            if (EPI <= 1 || EPI >= 5) {
                *(float4*)(Cfp + o) = make_float4(v[0], v[1], v[2], v[3]);
            } else {
                bf16 h[4], l[4];
                #pragma unroll
                for (int j = 0; j < 4; j++) split2(v[j], h[j], l[j]);
                ((__nv_bfloat162*)(Chp + o))[0] = __nv_bfloat162(h[0], h[1]);
                ((__nv_bfloat162*)(Chp + o))[1] = __nv_bfloat162(h[2], h[3]);
                ((__nv_bfloat162*)(Clp + o))[0] = __nv_bfloat162(l[0], l[1]);
                ((__nv_bfloat162*)(Clp + o))[1] = __nv_bfloat162(l[2], l[3]);
            }
        }
        __syncthreads();
    }

    if (EPI == 5 || EPI == 6) {
        #pragma unroll
        for (int it = 0; it < 4; it++) {
            #pragma unroll
            for (int o = 1; o < 8; o <<= 1) {
                float om = __shfl_xor_sync(0xffffffffu, stm[it], o);
                float oq = __shfl_xor_sync(0xffffffffu, stq[it], o);
                float nm = fmaxf(stm[it], om);
                stq[it] = stq[it] * __expf(stm[it] - nm) + oq * __expf(om - nm);
                stm[it] = nm;
            }
            if ((tid & 7) == 0) {
                int row = (it << 5) + (tid >> 3);
                long long so = ((long long)blockIdx.z * 2 + blockIdx.x) * 512 + m0 + row;
                statsp[so * 2]     = stm[it];
                statsp[so * 2 + 1] = stq[it];
            }
        }
    }

    TCGEN05_FENCE_BEFORE();
    __syncthreads();
    if (tid == 0) { MBARRIER_INVAL(mb0); MBARRIER_INVAL(mb1); }
    if (wid == 4) TCGEN05_DEALLOC(tmem, TN);
#else
    for (int o = tid; o < 128 * TN; o += 256) {
        int m = o / TN, n = o % TN;
        if (n >= nB) continue;
        float s = 0.f;
        const bf16* arh = Agh + (long long)m * lda;
        const bf16* arl = Agl + (long long)m * lda;
        const bf16* brh = Bgh + (long long)n * ldb;
        const bf16* brl = Bgl + (long long)n * ldb;
        for (int k = 0; k < K; k++)
            s += (__bfloat162float(arh[k]) + __bfloat162float(arl[k])) *
                 (__bfloat162float(brh[k]) + __bfloat162float(brl[k]));
        int gc = n0 + n;
        if (EPI == 1 || EPI == 2 || EPI == 4) s += bias[gc];
        if (EPI == 4) s = 0.5f * s * (1.0f + erff(s * 0.70710678118654752f));
        if (EPI == 5) s = 1.0f - s * cnp[(long long)blockIdx.z*512 + m0 + m] *
                              cnp[(long long)blockIdx.z*512 + gc]
                          + ((m0 + m) == gc ? 1.0f : 0.0f);
        if (EPI == 6) s *= 0.125f;
        long long off = (long long)(m0 + m) * ldc + gc;
        if (EPI <= 1 || EPI >= 5) Cfp[off] = s;
        else split2(s, Chp[off], Clp[off]);
    }
    if (EPI == 5 || EPI == 6) {
        __syncthreads();
        for (int m = tid; m < 128; m += 256) {
            float mm = -1e30f;
            for (int n = 0; n < nB; n++)
                mm = fmaxf(mm, Cfp[(long long)(m0 + m) * ldc + n0 + n]);
            float qq = 0.f;
            for (int n = 0; n < nB; n++)
                qq += __expf(Cfp[(long long)(m0 + m) * ldc + n0 + n] - mm);
            long long so = ((long long)blockIdx.z * 2 + blockIdx.x) * 512 + m0 + m;
            statsp[so * 2] = mm; statsp[so * 2 + 1] = qq;
        }
    }
#endif
}

// ---------------- combine per-tile stats -> (m, 0.5/sum) per row/branch ----------------
__global__ void combine_stats(const float* __restrict__ s1, const float* __restrict__ s2,
                              float* __restrict__ out)
{
    int i = blockIdx.x * 256 + threadIdx.x;       // 0 .. NBH*512
    int bh = i >> 9, r = i & 511;
    long long b0 = ((long long)bh * 2) * 512 + r;
    long long b1 = b0 + 512;
    float m0 = s1[b0*2], q0 = s1[b0*2+1], m1 = s1[b1*2], q1 = s1[b1*2+1];
    float m = fmaxf(m0, m1);
    float q = q0 * __expf(m0 - m) + q1 * __expf(m1 - m);
    float4 o;
    o.x = m; o.y = 0.5f / q;
    m0 = s2[b0*2]; q0 = s2[b0*2+1]; m1 = s2[b1*2]; q1 = s2[b1*2+1];
    m = fmaxf(m0, m1);
    q = q0 * __expf(m0 - m) + q1 * __expf(m1 - m);
    o.z = m; o.w = 0.5f / q;
    ((float4*)out)[i] = o;
}

// ---------------- ctx: P computed on-the-fly from S1/S2, MMA with V^T ----------------
#define CT_PH 0u
#define CT_PL 16384u
#define CT_VH 32768u
#define CT_VL 40960u
#define CT_ST 49152u
#define CT_CTL 51200u
#define CT_MBAR 51208u
#define CT_SMEM 51264
#define ID64C (0x8000490u | (8u << 17))

__global__ void __launch_bounds__(256) ctx_fused(
    const float* __restrict__ S1, const float* __restrict__ S2,
    const float* __restrict__ SM,
    const bf16* __restrict__ VTH, const bf16* __restrict__ VTL,
    bf16* __restrict__ OH, bf16* __restrict__ OL)
{
    extern __shared__ __align__(1024) char dsm[];
    const int tid = threadIdx.x, lane = tid & 31, wid = tid >> 5;
    const int m0 = blockIdx.x * 128, bh = blockIdx.y;
    const int zb = bh / NH, zh = bh % NH;

#if HAS_TC
    uint32_t sb = (uint32_t)__cvta_generic_to_shared(dsm);
    if (tid == 0) MBARRIER_INIT(sb + CT_MBAR, 1);
    if (wid == 4) { TCGEN05_ALLOC(sb + CT_CTL, 64); TCGEN05_RELINQ(); }
    __syncthreads();
    uint32_t tmem;
    asm volatile("ld.shared.b32 %0, [%1];" : "=r"(tmem) : "r"(sb + CT_CTL));
    int ph = 0;

    float4* stats = (float4*)(dsm + CT_ST);
    if (tid < 128) stats[tid] = ((const float4*)SM)[(long long)bh * 512 + m0 + tid];
    __syncthreads();

    const int r = tid >> 1, cb2 = (tid & 1) * 32;
    const float4 st = stats[r];
    const long long srow = ((long long)bh * 512 + m0 + r) * 512 + cb2;

    for (int j = 0; j < 8; j++) {
        const int k0 = j << 6;
        if (j > 0) { MBARRIER_WAIT_PARITY(sb + CT_MBAR, ph); ph ^= 1; }

        // B: V^T chunk (64 d-rows x 64 keys) hi/lo
        #pragma unroll
        for (int i = 0; i < 2; i++) {
            int id = tid + (i << 8);
            int vr = id >> 3, cc = id & 7;
            uint32_t off = (uint32_t)((vr << 7) + (cc << 4));
            uint32_t sw = off ^ ((off >> 3) & 0x70);
            long long g = (long long)bh * (64LL * 512) + (long long)vr * 512 + k0 + (cc << 3);
            cpa16(sb + CT_VH + sw, VTH + g, 16);
            cpa16(sb + CT_VL + sw, VTL + g, 16);
        }
        asm volatile("cp.async.commit_group;");

        // A: read S1/S2, compute P, split -> swizzled SMEM
        #pragma unroll
        for (int g = 0; g < 4; g++) {
            const float* p1 = S1 + srow + k0 + g * 8;
            const float* p2 = S2 + srow + k0 + g * 8;
            float4 a0 = ((const float4*)p1)[0], a1 = ((const float4*)p1)[1];
            float4 b0 = ((const float4*)p2)[0], b1 = ((const float4*)p2)[1];
            float s1v[8] = {a0.x, a0.y, a0.z, a0.w, a1.x, a1.y, a1.z, a1.w};
            float s2v[8] = {b0.x, b0.y, b0.z, b0.w, b1.x, b1.y, b1.z, b1.w};
            uint32_t H[4], L[4];
            #pragma unroll
            for (int e = 0; e < 4; e++) {
                float pa = __expf(s1v[e*2]   - st.x) * st.y + __expf(s2v[e*2]   - st.z) * st.w;
                float pb = __expf(s1v[e*2+1] - st.x) * st.y + __expf(s2v[e*2+1] - st.z) * st.w;
                bf16 h0, l0, h1, l1;
                split2(pa, h0, l0);
                split2(pb, h1, l1);
                H[e] = (uint32_t)__bfloat16_as_ushort(h0) | ((uint32_t)__bfloat16_as_ushort(h1) << 16);
                L[e] = (uint32_t)__bfloat16_as_ushort(l0) | ((uint32_t)__bfloat16_as_ushort(l1) << 16);
            }
            uint32_t off = (uint32_t)((r << 7) + ((cb2 + g * 8) << 1));
            uint32_t sw = off ^ ((off >> 3) & 0x70);
            STS128X(H[0], H[1], H[2], H[3], sb + CT_PH + sw);
            STS128X(L[0], L[1], L[2], L[3], sb + CT_PL + sw);
        }

        asm volatile("cp.async.wait_group 0;");
        FENCE_PROXY_ASYNC();
        __syncthreads();

        if (wid == 0) {
            if (elect_one_pred()) {
                uint64_t dA  = MAKE_SMEM_DESC(sb + CT_PH);
                uint64_t dAl = MAKE_SMEM_DESC(sb + CT_PL);
                uint64_t dB  = MAKE_SMEM_DESC(sb + CT_VH);
                uint64_t dBl = MAKE_SMEM_DESC(sb + CT_VL);
                #pragma unroll
                for (int s = 0; s < 4; s++) {
                    uint32_t en0 = (j == 0 && s == 0) ? 0u : 1u;
                    mma_f16_ss(tmem, dA + s*2, dB + s*2, ID64C, en0);
                    mma_f16_ss(tmem, dA + s*2, dBl + s*2, ID64C, 1u);
                    mma_f16_ss(tmem, dAl + s*2, dB + s*2, ID64C, 1u);
                }
                TCGEN05_COMMIT(sb + CT_MBAR);
            }
        }
    }
    MBARRIER_WAIT_PARITY(sb + CT_MBAR, ph);
    TCGEN05_FENCE_AFTER();

    // epilogue: pivot + coalesced pair stores (ctx cols 0..63)
    float* stg = (float*)dsm;
    __syncthreads();
    for (int cb = 0; cb < 64; cb += 32) {
        if (wid < 4) {
            uint32_t d[32];
            TCGEN05_LD_32X32B_X32(d, tmem + cb);
            TCGEN05_WAIT_LD();
            int row = (wid << 5) + lane;
            #pragma unroll
            for (int jj = 0; jj < 32; jj++) stg[row * 33 + jj] = __uint_as_float(d[jj]);
        }
        __syncthreads();
        #pragma unroll
        for (int it = 0; it < 4; it++) {
            int row = (it << 5) + (tid >> 3);
            int cc = (tid & 7) << 2;
            long long o = (long long)(zb * NS + m0 + row) * 768 + zh * 64 + cb + cc;
            bf16 h[4], l[4];
            #pragma unroll
            for (int jj = 0; jj < 4; jj++) split2(stg[row * 33 + cc + jj], h[jj], l[jj]);
            ((__nv_bfloat162*)(OH + o))[0] = __nv_bfloat162(h[0], h[1]);
            ((__nv_bfloat162*)(OH + o))[1] = __nv_bfloat162(h[2], h[3]);
            ((__nv_bfloat162*)(OL + o))[0] = __nv_bfloat162(l[0], l[1]);
            ((__nv_bfloat162*)(OL + o))[1] = __nv_bfloat162(l[2], l[3]);
        }
        __syncthreads();
    }

    TCGEN05_FENCE_BEFORE();
    __syncthreads();
    if (tid == 0) MBARRIER_INVAL(sb + CT_MBAR);
    if (wid == 4) TCGEN05_DEALLOC(tmem, 64);
#else
    // naive fallback (never selected on sm_103a hardware)
    for (int m = tid; m < 128; m += 256) {
        int grow = m0 + m;
        float4 st = ((const float4*)SM)[(long long)bh * 512 + grow];
        for (int d = 0; d < 64; d++) {
            float acc = 0.f;
            for (int rr = 0; rr < 512; rr++) {
                long long so = ((long long)bh * 512 + grow) * 512 + rr;
                float p = __expf(S1[so] - st.x) * st.y + __expf(S2[so] - st.z) * st.w;
                long long vo = (long long)bh * (64LL * 512) + (long long)d * 512 + rr;
                acc += p * (__bfloat162float(VTH[vo]) + __bfloat162float(VTL[vo]));
            }
            long long o = (long long)(zb * NS + grow) * 768 + zh * 64 + d;
            split2(acc, OH[o], OL[o]);
        }
    }
#endif
}

// ---------------- cnorm: 1/||c_r|| per (bh, r)  (validated in R9) ----------------
__global__ void cnorm_kernel(const bf16* __restrict__ ph, const bf16* __restrict__ pl,
                             float* __restrict__ cn)
{
    int w = (blockIdx.x << 3) + (threadIdx.x >> 5);
    int lane = threadIdx.x & 31;
    int bh = w >> 9, r = w & 511;
    int zb = bh / NH, zh = bh % NH;
    long long g = (long long)(zb * NS + r) * 3072 + 1536 + zh * 64 + lane * 2;
    float a = __bfloat162float(ph[g])     + __bfloat162float(pl[g]);
    float b = __bfloat162float(ph[g + 1]) + __bfloat162float(pl[g + 1]);
    float s = a * a + b * b;
    #pragma unroll
    for (int o = 16; o; o >>= 1) s += __shfl_xor_sync(0xffffffffu, s, o);
    if (lane == 0) cn[w] = rsqrtf(s);
}

// ---------------- fp32 -> bf16 hi/lo split ----------------
__global__ void conv_pair(const float4* __restrict__ src, bf16* __restrict__ h,
                          bf16* __restrict__ l, int n4)
{
    int i = blockIdx.x * 256 + threadIdx.x;
    if (i < n4) {
        float4 v = src[i];
        int b = i * 4;
        split2(v.x, h[b], l[b]);
        split2(v.y, h[b + 1], l[b + 1]);
        split2(v.z, h[b + 2], l[b + 2]);
        split2(v.w, h[b + 3], l[b + 3]);
    }
}

// ---------------- transpose + split ----------------
__global__ void transpose_split(const float* __restrict__ src, long long sS,
                                bf16* __restrict__ dh, bf16* __restrict__ dl, long long sD,
                                int R, int C, int lds, int ldd)
{
    __shared__ float t[32][33];
    const float* s = src + (long long)blockIdx.z * sS;
    bf16* oh = dh + (long long)blockIdx.z * sD;
    bf16* ol = dl + (long long)blockIdx.z * sD;
    int r0 = blockIdx.y * 32, c0 = blockIdx.x * 32;
    int tx = threadIdx.x, ty = threadIdx.y;
    #pragma unroll
    for (int i = 0; i < 4; i++) {
        int r = r0 + ty + i * 8;
        if (r < R && c0 + tx < C) t[ty + i * 8][tx] = s[(long long)r * lds + c0 + tx];
    }
    __syncthreads();
    #pragma unroll
    for (int i = 0; i < 4; i++) {
        int c = c0 + ty + i * 8, r = r0 + tx;
        if (c < C && r < R) {
            long long o = (long long)c * ldd + r;
            split2(t[tx][ty + i * 8], oh[o], ol[o]);
        }
    }
}

// ---------------- pair transpose (V -> Vt per head) ----------------
__global__ void transpose_pair(const bf16* __restrict__ sh, const bf16* __restrict__ sl,
                               long long sSb, long long sSh, int Hdiv,
                               bf16* __restrict__ dh, bf16* __restrict__ dl, long long sD,
                               int R, int C, int lds, int ldd)
{
    __shared__ uint32_t t[32][33];
    int zb = blockIdx.z / Hdiv, zh = blockIdx.z % Hdiv;
    long long so = zb * sSb + zh * sSh;
    bf16* oh = dh + (long long)blockIdx.z * sD;
    bf16* ol = dl + (long long)blockIdx.z * sD;
    int r0 = blockIdx.y * 32, c0 = blockIdx.x * 32;
    int tx = threadIdx.x, ty = threadIdx.y;
    #pragma unroll
    for (int i = 0; i < 4; i++) {
        int r = r0 + ty + i * 8;
        if (r < R && c0 + tx < C) {
            long long a = so + (long long)r * lds + c0 + tx;
            uint16_t hv = __bfloat16_as_ushort(sh[a]);
            uint16_t lv = __bfloat16_as_ushort(sl[a]);
            t[ty + i * 8][tx] = (uint32_t)hv | ((uint32_t)lv << 16);
        }
    }
    __syncthreads();
    #pragma unroll
    for (int i = 0; i < 4; i++) {
        int c = c0 + ty + i * 8, r = r0 + tx;
        if (c < C && r < R) {
            long long o = (long long)c * ldd + r;
            uint32_t v = t[tx][ty + i * 8];
            oh[o] = __ushort_as_bfloat16((uint16_t)(v & 0xffff));
            ol[o] = __ushort_as_bfloat16((uint16_t)(v >> 16));
        }
    }
}

// ---------------- block reduce (for LN) ----------------
__device__ __forceinline__ float block_reduce(float v, float* red)
{
    int lane = threadIdx.x & 31, w = threadIdx.x >> 5;
    #pragma unroll
    for (int o = 16; o; o >>= 1) v += __shfl_xor_sync(0xffffffffu, v, o);
    if (lane == 0) red[w] = v;
    __syncthreads();
    float r = red[0];
    #pragma unroll
    for (int i = 1; i < 8; i++) r += red[i];
    __syncthreads();
    return r;
}

// ---------------- residual add + LayerNorm ----------------
__global__ __launch_bounds__(256) void add_ln_kernel(
    const float* __restrict__ inp, const float* __restrict__ res,
    const float* __restrict__ g, const float* __restrict__ b,
    float* __restrict__ outf, bf16* __restrict__ outh, bf16* __restrict__ outl)
{
    long long row = blockIdx.x;
    const float* ip = inp + row * ND;
    const float* rp = res + row * ND;
    int t = threadIdx.x;

    __shared__ float buf[ND];
    __shared__ float red[8];

    float s = 0.f;
    for (int c = t; c < ND; c += 256) {
        float v = ip[c] + rp[c];
        buf[c] = v;
        s += v;
    }
    s = block_reduce(s, red);
    float mu = s * (1.0f / ND);
    float vs = 0.f;
    for (int c = t; c < ND; c += 256) {
        float d = buf[c] - mu;
        vs += d * d;
    }
    vs = block_reduce(vs, red);
    float inv = rsqrtf(vs * (1.0f / ND) + 1e-12f);
    for (int c = t; c < ND; c += 256) {
        float v = (buf[c] - mu) * inv * g[c] + b[c];
        long long o = row * ND + c;
        outf[o] = v;
        split2(v, outh[o], outl[o]);
    }
}

// ---------------- host ----------------
static float* symf(const void* s) { void* p = nullptr; cudaGetSymbolAddress(&p, s); return (float*)p; }
static bf16*  symb(const void* s) { void* p = nullptr; cudaGetSymbolAddress(&p, s); return (bf16*)p; }

#define SMEMSZ(TN, nst) ((nst) * ((128 + (TN)) * 256) + 64)

extern "C" void kernel_launch(void* const* d_in, const int* in_sizes, int n_in,
                              void* d_out, int out_size)
{
    const float* hs  = (const float*)d_in[0];
    const float* Wq  = (const float*)d_in[1];  const float* bq  = (const float*)d_in[2];
    const float* Wk  = (const float*)d_in[3];  const float* bk  = (const float*)d_in[4];
    const float* Wv  = (const float*)d_in[5];  const float* bv  = (const float*)d_in[6];
    const float* Wc  = (const float*)d_in[7];  const float* bc  = (const float*)d_in[8];
    const float* Wo  = (const float*)d_in[9];  const float* bo  = (const float*)d_in[10];
    const float* g1  = (const float*)d_in[11]; const float* b1  = (const float*)d_in[12];
    const float* Wi  = (const float*)d_in[13]; const float* bi  = (const float*)d_in[14];
    const float* Wo2 = (const float*)d_in[15]; const float* bo2 = (const float*)d_in[16];
    const float* g2  = (const float*)d_in[17]; const float* b2  = (const float*)d_in[18];

    const int SM256_2 = SMEMSZ(256, 2);
    const int SM256_1 = SMEMSZ(256, 1);

    cudaFuncSetAttribute(gemm_tc<1, 256>, cudaFuncAttributeMaxDynamicSharedMemorySize, SM256_2);
    cudaFuncSetAttribute(gemm_tc<2, 256>, cudaFuncAttributeMaxDynamicSharedMemorySize, SM256_2);
    cudaFuncSetAttribute(gemm_tc<4, 256>, cudaFuncAttributeMaxDynamicSharedMemorySize, SM256_2);
    cudaFuncSetAttribute(gemm_tc<5, 256>, cudaFuncAttributeMaxDynamicSharedMemorySize, SM256_1);
    cudaFuncSetAttribute(gemm_tc<6, 256>, cudaFuncAttributeMaxDynamicSharedMemorySize, SM256_1);
    cudaFuncSetAttribute(ctx_fused,       cudaFuncAttributeMaxDynamicSharedMemorySize, CT_SMEM);

    float* XF   = symf(g_xf);
    float* TMP  = symf(g_tmp);
    float* ATTF = symf(g_attnf);
    float* S1   = symf(g_s1);
    float* S2   = symf(g_s2);
    float* CN   = symf(g_cninv);
    float* ST1  = symf(g_st1);
    float* ST2  = symf(g_st2);
    float* SMC  = symf(g_smc);
    float* BCAT = symf(g_bcat);

    bf16 *XH = symb(g_xh), *XL = symb(g_xl);
    bf16 *PRJH = symb(g_prjh), *PRJL = symb(g_prjl);
    bf16 *CXH = symb(g_ctxh), *CXL = symb(g_ctxl);
    bf16 *ATH = symb(g_ath), *ATL = symb(g_atl);
    bf16 *HH = symb(g_hh), *HL = symb(g_hl);
    bf16 *VTH = symb(g_vth), *VTL = symb(g_vtl);

    bf16 *WCATH = symb(g_wcath), *WCATL = symb(g_wcatl);
    bf16 *WOH = symb(g_woh), *WOL = symb(g_wol);
    bf16 *WIH = symb(g_wih), *WIL = symb(g_wil);
    bf16 *WO2H = symb(g_wo2h), *WO2L = symb(g_wo2l);

    const long long SDP = (long long)NS * (4 * ND);
    const long long SS  = (long long)NS * NS;
    const long long HSS = (long long)NH * SS;
    const long long VTS = (long long)NDH * NS;

    const uint32_t ID256 = 0x8000490u | (32u << 17);

    dim3 tb(32, 8);
    transpose_split<<<dim3(24, 24, NL), tb>>>(Wq, WDD, WCATH + 0*WDD, WCATL + 0*WDD, CATW, 768, 768, 768, 768);
    transpose_split<<<dim3(24, 24, NL), tb>>>(Wk, WDD, WCATH + 1*WDD, WCATL + 1*WDD, CATW, 768, 768, 768, 768);
    transpose_split<<<dim3(24, 24, NL), tb>>>(Wc, WDD, WCATH + 2*WDD, WCATL + 2*WDD, CATW, 768, 768, 768, 768);
    transpose_split<<<dim3(24, 24, NL), tb>>>(Wv, WDD, WCATH + 3*WDD, WCATL + 3*WDD, CATW, 768, 768, 768, 768);
    transpose_split<<<dim3(24, 24, NL), tb>>>(Wo,  WDD, WOH,  WOL,  WDD, 768, 768, 768, 768);
    transpose_split<<<dim3(96, 24, NL), tb>>>(Wi,  WDF, WIH,  WIL,  WDF, 768, 3072, 3072, 768);
    transpose_split<<<dim3(24, 96, NL), tb>>>(Wo2, WDF, WO2H, WO2L, WDF, 3072, 768, 768, 3072);

    for (int i = 0; i < NL; i++) {
        cudaMemcpyAsync(BCAT + i*4*ND + 0*ND, bq + i*ND, ND*4, cudaMemcpyDeviceToDevice);
        cudaMemcpyAsync(BCAT + i*4*ND + 1*ND, bk + i*ND, ND*4, cudaMemcpyDeviceToDevice);
        cudaMemcpyAsync(BCAT + i*4*ND + 2*ND, bc + i*ND, ND*4, cudaMemcpyDeviceToDevice);
        cudaMemcpyAsync(BCAT + i*4*ND + 3*ND, bv + i*ND, ND*4, cudaMemcpyDeviceToDevice);
    }

    cudaMemcpyAsync(XF, hs, sizeof(float) * MROWS * ND, cudaMemcpyDeviceToDevice);
    conv_pair<<<(MROWS * ND / 4 + 255) / 256, 256>>>((const float4*)hs, XH, XL, MROWS * ND / 4);

    for (int i = 0; i < NL; i++) {
        const size_t oDD = (size_t)i * WDD, oDF = (size_t)i * WDF, oCAT = (size_t)i * CATW;

        // fused q|k|c|v projection
        gemm_tc<2, 256><<<dim3(12, 64, 1), 256, SM256_2>>>(
            XH, XL, 768, 0, 0, WCATH + oCAT, WCATL + oCAT, 768, 0, 0,
            nullptr, PRJH, PRJL, 3072, 0, 0, BCAT + i*4*ND, 3072, 768, 1, ID256,
            nullptr, nullptr);

        // V^T per head
        transpose_pair<<<dim3(2, 16, NBH), tb>>>(PRJH + 3*ND, PRJL + 3*ND, SDP, NDH, NH,
                                                 VTH, VTL, VTS, 512, 64, 4*ND, 512);

        // c-norms (direct, validated R9)
        cnorm_kernel<<<(NBH * NS) / 8, 256>>>(PRJH, PRJL, CN);

        // score GEMMs: S1 transformed cosine scores + stats, S2 scaled QK + stats
        dim3 gS(2, 4, NBH);
        gemm_tc<5, 256><<<gS, 256, SM256_1>>>(
            PRJH + 2*ND, PRJL + 2*ND, 4*ND, SDP, NDH,
            PRJH + 2*ND, PRJL + 2*ND, 4*ND, SDP, NDH,
            S1, nullptr, nullptr, 512, HSS, SS, nullptr, 512, 64, NH, ID256,
            CN, ST1);
        gemm_tc<6, 256><<<gS, 256, SM256_1>>>(
            PRJH + 0*ND, PRJL + 0*ND, 4*ND, SDP, NDH,
            PRJH + 1*ND, PRJL + 1*ND, 4*ND, SDP, NDH,
            S2, nullptr, nullptr, 512, HSS, SS, nullptr, 512, 64, NH, ID256,
            CN, ST2);

        // combine per-tile stats -> (m1, inv1, m2, inv2) per row
        combine_stats<<<(NBH * NS) / 256, 256>>>(ST1, ST2, SMC);

        // ctx = blendP(S1,S2) @ V^T  (P never materialized)
        ctx_fused<<<dim3(4, NBH), 256, CT_SMEM>>>(S1, S2, SMC, VTH, VTL, CXH, CXL);

        // attn_out = LN(ctx @ Wo + bo + x)
        gemm_tc<1, 256><<<dim3(3, 64, 1), 256, SM256_2>>>(
            CXH, CXL, 768, 0, 0, WOH + oDD, WOL + oDD, 768, 0, 0,
            TMP, nullptr, nullptr, 768, 0, 0, bo + i * ND, 768, 768, 1, ID256,
            nullptr, nullptr);
        add_ln_kernel<<<MROWS, 256>>>(TMP, XF, g1 + i * ND, b1 + i * ND, ATTF, ATH, ATL);

        // h = gelu(attn @ Wi + bi)
        gemm_tc<4, 256><<<dim3(12, 64, 1), 256, SM256_2>>>(
            ATH, ATL, 768, 0, 0, WIH + oDF, WIL + oDF, 768, 0, 0,
            nullptr, HH, HL, 3072, 0, 0, bi + i * NF, 3072, 768, 1, ID256,
            nullptr, nullptr);

        // x = LN(h @ Wo2 + bo2 + attn)
        gemm_tc<1, 256><<<dim3(3, 64, 1), 256, SM256_2>>>(
            HH, HL, 3072, 0, 0, WO2H + oDF, WO2L + oDF, 3072, 0, 0,
            TMP, nullptr, nullptr, 768, 0, 0, bo2 + i * ND, 768, 3072, 1, ID256,
            nullptr, nullptr);
        add_ln_kernel<<<MROWS, 256>>>(TMP, ATTF, g2 + i * ND, b2 + i * ND, XF, XH, XL);
    }

    cudaMemcpyAsync(d_out, XF, sizeof(float) * MROWS * ND, cudaMemcpyDeviceToDevice);
}

// round 11
// speedup vs baseline: 1.2545x; 1.2545x over previous
#include <cuda_runtime.h>
#include <cuda_bf16.h>
#include <math.h>
#include <stdint.h>

#define NH 12
#define NB 16
#define NS 512
#define ND 768
#define NF 3072
#define NL 4
#define NDH 64
#define MROWS (NB*NS)      // 8192
#define NBH (NB*NH)        // 192

typedef __nv_bfloat16 bf16;

#if defined(__CUDA_ARCH_FEAT_SM103_ALL)
#define HAS_TC 1
#else
#define HAS_TC 0
#endif

// ---------------- scratch ----------------
__device__ float g_xf[MROWS*ND];
__device__ float g_tmp[MROWS*ND];
__device__ float g_attnf[MROWS*ND];
__device__ float g_s1[(size_t)NBH*NS*NS];
__device__ float g_s2[(size_t)NBH*NS*NS];
__device__ float g_cninv[NBH*NS];

__device__ bf16 g_xh[MROWS*ND],   g_xl[MROWS*ND];
__device__ bf16 g_prjh[(size_t)MROWS*4*ND], g_prjl[(size_t)MROWS*4*ND]; // q|k|c|v
__device__ bf16 g_ctxh[MROWS*ND], g_ctxl[MROWS*ND];
__device__ bf16 g_ath[MROWS*ND],  g_atl[MROWS*ND];
__device__ bf16 g_hh[(size_t)MROWS*NF], g_hl[(size_t)MROWS*NF];
__device__ bf16 g_ph[(size_t)NBH*NS*NS], g_pl[(size_t)NBH*NS*NS];
__device__ bf16 g_vth[NBH*NDH*NS], g_vtl[NBH*NDH*NS];

#define WDD (768*768)
#define WDF (768*3072)
#define CATW (4*WDD)
__device__ bf16 g_wcath[NL*CATW], g_wcatl[NL*CATW];
__device__ bf16 g_woh[NL*WDD], g_wol[NL*WDD];
__device__ bf16 g_wih[NL*WDF], g_wil[NL*WDF];
__device__ bf16 g_wo2h[NL*WDF], g_wo2l[NL*WDF];
__device__ float g_bcat[NL*4*ND];

// ---------------- helpers ----------------
__device__ __forceinline__ void split2(float v, bf16& h, bf16& l) {
    h = __float2bfloat16(v);
    l = __float2bfloat16(v - __bfloat162float(h));
}

__device__ __forceinline__ void cpa16(uint32_t dst, const void* src, int sz) {
    asm volatile("cp.async.cg.shared.global [%0], [%1], 16, %2;" :: "r"(dst), "l"(src), "r"(sz));
}

#define FENCE_PROXY_ASYNC() \
    asm volatile("fence.proxy.async.shared::cta;" ::: "memory")

#if HAS_TC
__device__ __forceinline__ uint32_t elect_one_pred() {
    uint32_t pred;
    asm volatile(
        "{\n\t.reg .pred p;\n\t"
        "elect.sync _|p, 0xFFFFFFFF;\n\t"
        "selp.b32 %0, 1, 0, p;\n\t}"
        : "=r"(pred));
    return pred;
}

static constexpr uint64_t SMEM_DESC_BASE_SW128 =
    (uint64_t(2) << 61) | (uint64_t(1) << 46) | (uint64_t(64) << 32) | (uint64_t(1) << 16);
#define MAKE_SMEM_DESC(base_addr) \
    (SMEM_DESC_BASE_SW128 | ((uint64_t)((base_addr) >> 4) & 0x3FFF))

#define TCGEN05_ALLOC(smem_result_addr, nCols) \
    asm volatile("tcgen05.alloc.cta_group::1.sync.aligned.shared::cta.b32 [%0], %1;" \
        :: "r"((uint32_t)(smem_result_addr)), "r"((uint32_t)(nCols)) : "memory")
#define TCGEN05_DEALLOC(tmem_addr, nCols) \
    asm volatile("tcgen05.dealloc.cta_group::1.sync.aligned.b32 %0, %1;" \
        :: "r"(tmem_addr), "r"((uint32_t)(nCols)))
#define TCGEN05_RELINQ() \
    asm volatile("tcgen05.relinquish_alloc_permit.cta_group::1.sync.aligned;")
#define TCGEN05_COMMIT(mbar) \
    asm volatile("tcgen05.commit.cta_group::1.mbarrier::arrive::one.shared::cluster.b64 [%0];" \
        :: "r"((uint32_t)(mbar)) : "memory")
#define TCGEN05_WAIT_LD() \
    asm volatile("tcgen05.wait::ld.sync.aligned;" ::: "memory")
#define TCGEN05_FENCE_AFTER() \
    asm volatile("tcgen05.fence::after_thread_sync;" ::: "memory")
#define TCGEN05_FENCE_BEFORE() \
    asm volatile("tcgen05.fence::before_thread_sync;" ::: "memory")

#define MBARRIER_INIT(mbar, count) \
    asm volatile("mbarrier.init.shared.b64 [%0], %1;" \
        :: "r"((uint32_t)(mbar)), "r"((uint32_t)(count)) : "memory")
#define MBARRIER_INVAL(mbar) \
    asm volatile("mbarrier.inval.shared.b64 [%0];" :: "r"((uint32_t)(mbar)) : "memory")
#define MBARRIER_WAIT_PARITY(mbar_addr, phase_parity) do { \
    uint32_t _mbar = (uint32_t)(mbar_addr); \
    uint32_t _parity = (uint32_t)(phase_parity); \
    uint32_t _done; \
    asm volatile( \
        "{\n\t.reg .pred p;\n\t" \
        "mbarrier.try_wait.parity.acquire.cta.shared::cta.b64 p, [%1], %2;\n\t" \
        "selp.b32 %0, 1, 0, p;\n\t}" \
        : "=r"(_done) : "r"(_mbar), "r"(_parity) : "memory"); \
    if (!_done) { \
        asm volatile( \
            "{\n\t.reg .pred P1;\n\t" \
            "WAIT_LOOP_%=:\n\t" \
            "mbarrier.try_wait.parity.acquire.cta.shared::cta.b64 P1, [%0], %1, 0x989680;\n\t" \
            "@P1 bra.uni WAIT_DONE_%=;\n\t" \
            "bra.uni WAIT_LOOP_%=;\n\t" \
            "WAIT_DONE_%=:\n\t}" \
            :: "r"(_mbar), "r"(_parity) : "memory"); \
    } \
} while(0)

#define TCGEN05_LD_32X32B_X32(r, tmem_addr) \
    asm volatile( \
        "tcgen05.ld.sync.aligned.32x32b.x32.b32 " \
        "{%0, %1, %2, %3, %4, %5, %6, %7, " \
        " %8, %9, %10, %11, %12, %13, %14, %15, " \
        " %16, %17, %18, %19, %20, %21, %22, %23, " \
        " %24, %25, %26, %27, %28, %29, %30, %31}, [%32];" \
        : "=r"((r)[0]),  "=r"((r)[1]),  "=r"((r)[2]),  "=r"((r)[3]), \
          "=r"((r)[4]),  "=r"((r)[5]),  "=r"((r)[6]),  "=r"((r)[7]), \
          "=r"((r)[8]),  "=r"((r)[9]),  "=r"((r)[10]), "=r"((r)[11]), \
          "=r"((r)[12]), "=r"((r)[13]), "=r"((r)[14]), "=r"((r)[15]), \
          "=r"((r)[16]), "=r"((r)[17]), "=r"((r)[18]), "=r"((r)[19]), \
          "=r"((r)[20]), "=r"((r)[21]), "=r"((r)[22]), "=r"((r)[23]), \
          "=r"((r)[24]), "=r"((r)[25]), "=r"((r)[26]), "=r"((r)[27]), \
          "=r"((r)[28]), "=r"((r)[29]), "=r"((r)[30]), "=r"((r)[31]) \
        : "r"(tmem_addr))

__device__ __forceinline__ void mma_f16_ss(uint32_t d, uint64_t ad, uint64_t bd,
                                           uint32_t idesc, uint32_t en) {
    asm volatile(
        "{\n\t.reg .pred p;\n\t"
        "setp.ne.u32 p, %5, 0;\n\t"
        "tcgen05.mma.cta_group::1.kind::f16 [%0], %1, %2, %3, {%4, %4, %4, %4}, p;\n\t}"
        :: "r"(d), "l"(ad), "l"(bd), "r"(idesc), "r"(0u), "r"(en) : "memory");
}
#endif

// ---------------- bf16x3 NT GEMM, TN-templated tile (128 x TN) ----------------
// C[m,n] = sum_k (Ahi+Alo)[m,k]*(Bhi+Blo)[n,k]
// EPI: 0 f32, 1 f32+bias, 2 pair+bias, 3 pair, 4 pair+bias+gelu
// stages: 1 if K<=64 else 2 (host passes matching dynamic smem size)
template<int EPI, int TN>
__global__ void __launch_bounds__(256) gemm_tc(
    const bf16* __restrict__ Ah_, const bf16* __restrict__ Al_,
    int lda, long long sAb, long long sAh,
    const bf16* __restrict__ Bh_, const bf16* __restrict__ Bl_,
    int ldb, long long sBb, long long sBh,
    float* __restrict__ Cf, bf16* __restrict__ Coh, bf16* __restrict__ Col,
    int ldc, long long sCb, long long sCh,
    const float* __restrict__ bias,
    int N, int K, int Hdiv, uint32_t idesc)
{
    constexpr int STAGE = (128 + TN) * 256;
    constexpr int AHOF = 0, ALOF = 16384, BHOF = 32768, BLOF = 32768 + TN * 128;
    extern __shared__ __align__(1024) char dsm[];
    const int tid = threadIdx.x, lane = tid & 31, wid = tid >> 5;
    const int zb = blockIdx.z / Hdiv, zh = blockIdx.z % Hdiv;
    const int m0 = blockIdx.y * 128, n0 = blockIdx.x * TN;
    const int nB = min(TN, N - n0);

    const bf16* Agh = Ah_ + zb*sAb + zh*sAh + (long long)m0 * lda;
    const bf16* Agl = Al_ + zb*sAb + zh*sAh + (long long)m0 * lda;
    const bf16* Bgh = Bh_ + zb*sBb + zh*sBh + (long long)n0 * ldb;
    const bf16* Bgl = Bl_ + zb*sBb + zh*sBh + (long long)n0 * ldb;

    float* Cfp = Cf  ? Cf  + zb*sCb + zh*sCh : nullptr;
    bf16*  Chp = Coh ? Coh + zb*sCb + zh*sCh : nullptr;
    bf16*  Clp = Col ? Col + zb*sCb + zh*sCh : nullptr;

#if HAS_TC
    const int nst = (K > 64) ? 2 : 1;
    uint32_t sb  = (uint32_t)__cvta_generic_to_shared(dsm);
    uint32_t ctl = sb + (uint32_t)(nst * STAGE);
    uint32_t mb0 = ctl + 8, mb1 = ctl + 16;

    if (tid == 0) { MBARRIER_INIT(mb0, 1); MBARRIER_INIT(mb1, 1); }
    if (wid == 4) { TCGEN05_ALLOC(ctl, TN); TCGEN05_RELINQ(); }
    __syncthreads();
    uint32_t tmem;
    asm volatile("ld.shared.b32 %0, [%1];" : "=r"(tmem) : "r"(ctl));

    const int KT = K >> 6;
    int ph0 = 0, ph1 = 0;

    auto issue = [&](int buf, int k0) {
        const uint32_t sbase = sb + (uint32_t)(buf * STAGE);
        constexpr int ITER = (128 + TN) * 8 / 256;
        #pragma unroll
        for (int i = 0; i < ITER; i++) {
            int id = tid + (i << 8);
            int row = id >> 3, cc = id & 7;
            if (row < 128) {
                uint32_t off = (uint32_t)((row << 7) + (cc << 4));
                uint32_t sw = off ^ ((off >> 3) & 0x70);
                long long ga = (long long)row * lda + k0 + (cc << 3);
                cpa16(sbase + AHOF + sw, Agh + ga, 16);
                cpa16(sbase + ALOF + sw, Agl + ga, 16);
            } else {
                int rb = row - 128;
                uint32_t off = (uint32_t)((rb << 7) + (cc << 4));
                uint32_t sw = off ^ ((off >> 3) & 0x70);
                int sz = 16, br = rb;
                if (rb >= nB) { sz = 0; br = 0; }
                long long gb = (long long)br * ldb + k0 + (cc << 3);
                cpa16(sbase + BHOF + sw, Bgh + gb, sz);
                cpa16(sbase + BLOF + sw, Bgl + gb, sz);
            }
        }
        asm volatile("cp.async.commit_group;");
    };

    issue(0, 0);
    for (int kt = 0; kt < KT; kt++) {
        const int buf = (nst == 2) ? (kt & 1) : 0;
        if (kt + 1 < KT) {
            if (kt >= 1) {
                if ((buf ^ 1) == 0) { MBARRIER_WAIT_PARITY(mb0, ph0); ph0 ^= 1; }
                else                { MBARRIER_WAIT_PARITY(mb1, ph1); ph1 ^= 1; }
            }
            issue(buf ^ 1, (kt + 1) << 6);
            asm volatile("cp.async.wait_group 1;");
        } else {
            asm volatile("cp.async.wait_group 0;");
        }
        FENCE_PROXY_ASYNC();
        __syncthreads();

        const uint32_t sbase = sb + (uint32_t)(buf * STAGE);
        if (wid == 4) {
            if (elect_one_pred()) {
                uint64_t dah = MAKE_SMEM_DESC(sbase + AHOF);
                uint64_t dal = MAKE_SMEM_DESC(sbase + ALOF);
                uint64_t dbh = MAKE_SMEM_DESC(sbase + BHOF);
                uint64_t dbl = MAKE_SMEM_DESC(sbase + BLOF);
                #pragma unroll
                for (int s = 0; s < 4; s++) {
                    uint32_t en0 = (kt == 0 && s == 0) ? 0u : 1u;
                    mma_f16_ss(tmem, dah + s*2, dbh + s*2, idesc, en0);
                    mma_f16_ss(tmem, dah + s*2, dbl + s*2, idesc, 1u);
                    mma_f16_ss(tmem, dal + s*2, dbh + s*2, idesc, 1u);
                }
                TCGEN05_COMMIT(buf ? mb1 : mb0);
            }
        }
        __syncthreads();
    }

    const int lastbuf = (nst == 2) ? ((KT - 1) & 1) : 0;
    if (lastbuf == 0) { MBARRIER_WAIT_PARITY(mb0, ph0); }
    else              { MBARRIER_WAIT_PARITY(mb1, ph1); }
    TCGEN05_FENCE_AFTER();

    // epilogue: TMEM -> SMEM pivot -> coalesced stores (R5/R8 proven)
    float* stg = (float*)dsm;
    for (int cb = 0; cb < nB; cb += 32) {
        if (wid < 4) {
            uint32_t d[32];
            TCGEN05_LD_32X32B_X32(d, tmem + cb);
            TCGEN05_WAIT_LD();
            int row = (wid << 5) + lane;
            #pragma unroll
            for (int j = 0; j < 32; j++) stg[row * 33 + j] = __uint_as_float(d[j]);
        }
        __syncthreads();
        #pragma unroll
        for (int it = 0; it < 4; it++) {
            int row = (it << 5) + (tid >> 3);
            int cc = (tid & 7) << 2;
            int gc = n0 + cb + cc;
            long long o = (long long)(m0 + row) * ldc + gc;
            float v[4];
            #pragma unroll
            for (int j = 0; j < 4; j++) {
                v[j] = stg[row * 33 + cc + j];
                if (EPI == 1 || EPI == 2 || EPI == 4) v[j] += bias[gc + j];
                if (EPI == 4) v[j] = 0.5f * v[j] * (1.0f + erff(v[j] * 0.70710678118654752f));
            }
            if (EPI <= 1) {
                *(float4*)(Cfp + o) = make_float4(v[0], v[1], v[2], v[3]);
            } else {
                bf16 h[4], l[4];
                #pragma unroll
                for (int j = 0; j < 4; j++) split2(v[j], h[j], l[j]);
                ((__nv_bfloat162*)(Chp + o))[0] = __nv_bfloat162(h[0], h[1]);
                ((__nv_bfloat162*)(Chp + o))[1] = __nv_bfloat162(h[2], h[3]);
                ((__nv_bfloat162*)(Clp + o))[0] = __nv_bfloat162(l[0], l[1]);
                ((__nv_bfloat162*)(Clp + o))[1] = __nv_bfloat162(l[2], l[3]);
            }
        }
        __syncthreads();
    }

    TCGEN05_FENCE_BEFORE();
    __syncthreads();
    if (tid == 0) { MBARRIER_INVAL(mb0); MBARRIER_INVAL(mb1); }
    if (wid == 4) TCGEN05_DEALLOC(tmem, TN);
#else
    // trivially-correct scalar fallback (never selected on sm_103a hardware)
    for (int o = tid; o < 128 * TN; o += 256) {
        int m = o / TN, n = o % TN;
        if (n >= nB) continue;
        float s = 0.f;
        const bf16* arh = Agh + (long long)m * lda;
        const bf16* arl = Agl + (long long)m * lda;
        const bf16* brh = Bgh + (long long)n * ldb;
        const bf16* brl = Bgl + (long long)n * ldb;
        for (int k = 0; k < K; k++)
            s += (__bfloat162float(arh[k]) + __bfloat162float(arl[k])) *
                 (__bfloat162float(brh[k]) + __bfloat162float(brl[k]));
        int gc = n0 + n;
        if (EPI == 1 || EPI == 2 || EPI == 4) s += bias[gc];
        if (EPI == 4) s = 0.5f * s * (1.0f + erff(s * 0.70710678118654752f));
        long long off = (long long)(m0 + m) * ldc + gc;
        if (EPI <= 1) Cfp[off] = s;
        else split2(s, Chp[off], Clp[off]);
    }
#endif
}

// ---------------- fp32 -> bf16 hi/lo split ----------------
__global__ void conv_pair(const float4* __restrict__ src, bf16* __restrict__ h,
                          bf16* __restrict__ l, int n4)
{
    int i = blockIdx.x * 256 + threadIdx.x;
    if (i < n4) {
        float4 v = src[i];
        int b = i * 4;
        split2(v.x, h[b], l[b]);
        split2(v.y, h[b + 1], l[b + 1]);
        split2(v.z, h[b + 2], l[b + 2]);
        split2(v.w, h[b + 3], l[b + 3]);
    }
}

// ---------------- transpose + split: fp32 [R,C] -> bf16 pair [C,R] ----------------
__global__ void transpose_split(const float* __restrict__ src, long long sS,
                                bf16* __restrict__ dh, bf16* __restrict__ dl, long long sD,
                                int R, int C, int lds, int ldd)
{
    __shared__ float t[32][33];
    const float* s = src + (long long)blockIdx.z * sS;
    bf16* oh = dh + (long long)blockIdx.z * sD;
    bf16* ol = dl + (long long)blockIdx.z * sD;
    int r0 = blockIdx.y * 32, c0 = blockIdx.x * 32;
    int tx = threadIdx.x, ty = threadIdx.y;
    #pragma unroll
    for (int i = 0; i < 4; i++) {
        int r = r0 + ty + i * 8;
        if (r < R && c0 + tx < C) t[ty + i * 8][tx] = s[(long long)r * lds + c0 + tx];
    }
    __syncthreads();
    #pragma unroll
    for (int i = 0; i < 4; i++) {
        int c = c0 + ty + i * 8, r = r0 + tx;
        if (c < C && r < R) {
            long long o = (long long)c * ldd + r;
            split2(t[tx][ty + i * 8], oh[o], ol[o]);
        }
    }
}

// ---------------- pair transpose: bf16 pair [R,C] -> bf16 pair [C,R] ----------------
__global__ void transpose_pair(const bf16* __restrict__ sh, const bf16* __restrict__ sl,
                               long long sSb, long long sSh, int Hdiv,
                               bf16* __restrict__ dh, bf16* __restrict__ dl, long long sD,
                               int R, int C, int lds, int ldd)
{
    __shared__ uint32_t t[32][33];
    int zb = blockIdx.z / Hdiv, zh = blockIdx.z % Hdiv;
    long long so = zb * sSb + zh * sSh;
    bf16* oh = dh + (long long)blockIdx.z * sD;
    bf16* ol = dl + (long long)blockIdx.z * sD;
    int r0 = blockIdx.y * 32, c0 = blockIdx.x * 32;
    int tx = threadIdx.x, ty = threadIdx.y;
    #pragma unroll
    for (int i = 0; i < 4; i++) {
        int r = r0 + ty + i * 8;
        if (r < R && c0 + tx < C) {
            long long a = so + (long long)r * lds + c0 + tx;
            uint16_t hv = __bfloat16_as_ushort(sh[a]);
            uint16_t lv = __bfloat16_as_ushort(sl[a]);
            t[ty + i * 8][tx] = (uint32_t)hv | ((uint32_t)lv << 16);
        }
    }
    __syncthreads();
    #pragma unroll
    for (int i = 0; i < 4; i++) {
        int c = c0 + ty + i * 8, r = r0 + tx;
        if (c < C && r < R) {
            long long o = (long long)c * ldd + r;
            uint32_t v = t[tx][ty + i * 8];
            oh[o] = __ushort_as_bfloat16((uint16_t)(v & 0xffff));
            ol[o] = __ushort_as_bfloat16((uint16_t)(v >> 16));
        }
    }
}

// ---------------- diag -> 1/||c|| ----------------
__global__ void diag_rsqrt_kernel(const float* __restrict__ Gc, float* __restrict__ cninv)
{
    int i = blockIdx.x * 256 + threadIdx.x;
    if (i < NBH * NS) {
        int bh = i / NS, s = i % NS;
        cninv[i] = rsqrtf(Gc[((long long)bh * NS + s) * NS + s]);
    }
}

// ---------------- blend + dual softmax: 1 warp per row ----------------
__global__ __launch_bounds__(256) void blend_softmax2(
    const float* __restrict__ Gc, const float* __restrict__ Gqk,
    const float* __restrict__ cninv, bf16* __restrict__ ph, bf16* __restrict__ pl)
{
    const int lane = threadIdx.x & 31, wid = threadIdx.x >> 5;
    const int row = blockIdx.x * 8 + wid;
    const int bh = blockIdx.y;
    const long long base = ((long long)bh * NS + row) * NS;
    const float4* gc4 = (const float4*)(Gc + base);
    const float4* gq4 = (const float4*)(Gqk + base);
    const float4* cn4 = (const float4*)(cninv + bh * NS);
    const float cl = cninv[bh * NS + row];

    float s1[16], s2[16];
    #pragma unroll
    for (int j = 0; j < 4; j++) {
        int idx = j * 32 + lane;
        float4 g = gc4[idx];
        float4 q = gq4[idx];
        float4 cr = cn4[idx];
        int c0 = idx * 4;
        s1[j*4+0] = 1.0f - g.x * cl * cr.x + (c0     == row ? 1.0f : 0.0f);
        s1[j*4+1] = 1.0f - g.y * cl * cr.y + (c0 + 1 == row ? 1.0f : 0.0f);
        s1[j*4+2] = 1.0f - g.z * cl * cr.z + (c0 + 2 == row ? 1.0f : 0.0f);
        s1[j*4+3] = 1.0f - g.w * cl * cr.w + (c0 + 3 == row ? 1.0f : 0.0f);
        s2[j*4+0] = q.x * 0.125f;
        s2[j*4+1] = q.y * 0.125f;
        s2[j*4+2] = q.z * 0.125f;
        s2[j*4+3] = q.w * 0.125f;
    }
    float m1 = -1e30f, m2 = -1e30f;
    #pragma unroll
    for (int j = 0; j < 16; j++) { m1 = fmaxf(m1, s1[j]); m2 = fmaxf(m2, s2[j]); }
    #pragma unroll
    for (int o = 16; o; o >>= 1) {
        m1 = fmaxf(m1, __shfl_xor_sync(0xffffffffu, m1, o));
        m2 = fmaxf(m2, __shfl_xor_sync(0xffffffffu, m2, o));
    }
    float sum1 = 0.f, sum2 = 0.f;
    #pragma unroll
    for (int j = 0; j < 16; j++) {
        s1[j] = __expf(s1[j] - m1); sum1 += s1[j];
        s2[j] = __expf(s2[j] - m2); sum2 += s2[j];
    }
    #pragma unroll
    for (int o = 16; o; o >>= 1) {
        sum1 += __shfl_xor_sync(0xffffffffu, sum1, o);
        sum2 += __shfl_xor_sync(0xffffffffu, sum2, o);
    }
    float inv1 = 0.5f / sum1, inv2 = 0.5f / sum2;
    #pragma unroll
    for (int j = 0; j < 4; j++) {
        int c0 = (j * 32 + lane) * 4;
        __nv_bfloat162 h2[2], l2[2];
        #pragma unroll
        for (int e = 0; e < 4; e++) {
            float p = s1[j*4+e] * inv1 + s2[j*4+e] * inv2;
            bf16 h, l;
            split2(p, h, l);
            ((bf16*)h2)[e] = h;
            ((bf16*)l2)[e] = l;
        }
        *(uint2*)(ph + base + c0) = *(uint2*)h2;
        *(uint2*)(pl + base + c0) = *(uint2*)l2;
    }
}

// ---------------- block reduce (for LN) ----------------
__device__ __forceinline__ float block_reduce(float v, float* red)
{
    int lane = threadIdx.x & 31, w = threadIdx.x >> 5;
    #pragma unroll
    for (int o = 16; o; o >>= 1) v += __shfl_xor_sync(0xffffffffu, v, o);
    if (lane == 0) red[w] = v;
    __syncthreads();
    float r = red[0];
    #pragma unroll
    for (int i = 1; i < 8; i++) r += red[i];
    __syncthreads();
    return r;
}

// ---------------- residual add + LayerNorm ----------------
__global__ __launch_bounds__(256) void add_ln_kernel(
    const float* __restrict__ inp, const float* __restrict__ res,
    const float* __restrict__ g, const float* __restrict__ b,
    float* __restrict__ outf, bf16* __restrict__ outh, bf16* __restrict__ outl)
{
    long long row = blockIdx.x;
    const float* ip = inp + row * ND;
    const float* rp = res + row * ND;
    int t = threadIdx.x;

    __shared__ float buf[ND];
    __shared__ float red[8];

    float s = 0.f;
    for (int c = t; c < ND; c += 256) {
        float v = ip[c] + rp[c];
        buf[c] = v;
        s += v;
    }
    s = block_reduce(s, red);
    float mu = s * (1.0f / ND);
    float vs = 0.f;
    for (int c = t; c < ND; c += 256) {
        float d = buf[c] - mu;
        vs += d * d;
    }
    vs = block_reduce(vs, red);
    float inv = rsqrtf(vs * (1.0f / ND) + 1e-12f);
    for (int c = t; c < ND; c += 256) {
        float v = (buf[c] - mu) * inv * g[c] + b[c];
        long long o = row * ND + c;
        outf[o] = v;
        split2(v, outh[o], outl[o]);
    }
}

// ---------------- host ----------------
static float* symf(const void* s) { void* p = nullptr; cudaGetSymbolAddress(&p, s); return (float*)p; }
static bf16*  symb(const void* s) { void* p = nullptr; cudaGetSymbolAddress(&p, s); return (bf16*)p; }

#define SMEMSZ(TN, nst) ((nst) * ((128 + (TN)) * 256) + 64)

extern "C" void kernel_launch(void* const* d_in, const int* in_sizes, int n_in,
                              void* d_out, int out_size)
{
    const float* hs  = (const float*)d_in[0];
    const float* Wq  = (const float*)d_in[1];  const float* bq  = (const float*)d_in[2];
    const float* Wk  = (const float*)d_in[3];  const float* bk  = (const float*)d_in[4];
    const float* Wv  = (const float*)d_in[5];  const float* bv  = (const float*)d_in[6];
    const float* Wc  = (const float*)d_in[7];  const float* bc  = (const float*)d_in[8];
    const float* Wo  = (const float*)d_in[9];  const float* bo  = (const float*)d_in[10];
    const float* g1  = (const float*)d_in[11]; const float* b1  = (const float*)d_in[12];
    const float* Wi  = (const float*)d_in[13]; const float* bi  = (const float*)d_in[14];
    const float* Wo2 = (const float*)d_in[15]; const float* bo2 = (const float*)d_in[16];
    const float* g2  = (const float*)d_in[17]; const float* b2  = (const float*)d_in[18];

    const int SM256_2 = SMEMSZ(256, 2);
    const int SM256_1 = SMEMSZ(256, 1);
    const int SM128_2 = SMEMSZ(128, 2);
    const int SM64_2  = SMEMSZ(64, 2);

    cudaFuncSetAttribute(gemm_tc<0, 256>, cudaFuncAttributeMaxDynamicSharedMemorySize, SM256_2);
    cudaFuncSetAttribute(gemm_tc<1, 128>, cudaFuncAttributeMaxDynamicSharedMemorySize, SM128_2);
    cudaFuncSetAttribute(gemm_tc<2, 256>, cudaFuncAttributeMaxDynamicSharedMemorySize, SM256_2);
    cudaFuncSetAttribute(gemm_tc<4, 256>, cudaFuncAttributeMaxDynamicSharedMemorySize, SM256_2);
    cudaFuncSetAttribute(gemm_tc<3, 64>,  cudaFuncAttributeMaxDynamicSharedMemorySize, SM64_2);

    float* XF   = symf(g_xf);
    float* TMP  = symf(g_tmp);
    float* ATTF = symf(g_attnf);
    float* S1   = symf(g_s1);
    float* S2   = symf(g_s2);
    float* CN   = symf(g_cninv);
    float* BCAT = symf(g_bcat);

    bf16 *XH = symb(g_xh), *XL = symb(g_xl);
    bf16 *PRJH = symb(g_prjh), *PRJL = symb(g_prjl);
    bf16 *CXH = symb(g_ctxh), *CXL = symb(g_ctxl);
    bf16 *ATH = symb(g_ath), *ATL = symb(g_atl);
    bf16 *HH = symb(g_hh), *HL = symb(g_hl);
    bf16 *PH = symb(g_ph), *PL = symb(g_pl);
    bf16 *VTH = symb(g_vth), *VTL = symb(g_vtl);

    bf16 *WCATH = symb(g_wcath), *WCATL = symb(g_wcatl);
    bf16 *WOH = symb(g_woh), *WOL = symb(g_wol);
    bf16 *WIH = symb(g_wih), *WIL = symb(g_wil);
    bf16 *WO2H = symb(g_wo2h), *WO2L = symb(g_wo2l);

    const long long SD   = (long long)NS * ND;
    const long long SDP  = (long long)NS * (4 * ND);
    const long long SS   = (long long)NS * NS;
    const long long HSS  = (long long)NH * SS;
    const long long VTS  = (long long)NDH * NS;

    const uint32_t ID256 = 0x8000490u | (32u << 17);
    const uint32_t ID128 = 0x8000490u | (16u << 17);
    const uint32_t ID64  = 0x8000490u | (8u << 17);

    dim3 tb(32, 8);
    transpose_split<<<dim3(24, 24, NL), tb>>>(Wq, WDD, WCATH + 0*WDD, WCATL + 0*WDD, CATW, 768, 768, 768, 768);
    transpose_split<<<dim3(24, 24, NL), tb>>>(Wk, WDD, WCATH + 1*WDD, WCATL + 1*WDD, CATW, 768, 768, 768, 768);
    transpose_split<<<dim3(24, 24, NL), tb>>>(Wc, WDD, WCATH + 2*WDD, WCATL + 2*WDD, CATW, 768, 768, 768, 768);
    transpose_split<<<dim3(24, 24, NL), tb>>>(Wv, WDD, WCATH + 3*WDD, WCATL + 3*WDD, CATW, 768, 768, 768, 768);
    transpose_split<<<dim3(24, 24, NL), tb>>>(Wo,  WDD, WOH,  WOL,  WDD, 768, 768, 768, 768);
    transpose_split<<<dim3(96, 24, NL), tb>>>(Wi,  WDF, WIH,  WIL,  WDF, 768, 3072, 3072, 768);
    transpose_split<<<dim3(24, 96, NL), tb>>>(Wo2, WDF, WO2H, WO2L, WDF, 3072, 768, 768, 3072);

    for (int i = 0; i < NL; i++) {
        cudaMemcpyAsync(BCAT + i*4*ND + 0*ND, bq + i*ND, ND*4, cudaMemcpyDeviceToDevice);
        cudaMemcpyAsync(BCAT + i*4*ND + 1*ND, bk + i*ND, ND*4, cudaMemcpyDeviceToDevice);
        cudaMemcpyAsync(BCAT + i*4*ND + 2*ND, bc + i*ND, ND*4, cudaMemcpyDeviceToDevice);
        cudaMemcpyAsync(BCAT + i*4*ND + 3*ND, bv + i*ND, ND*4, cudaMemcpyDeviceToDevice);
    }

    cudaMemcpyAsync(XF, hs, sizeof(float) * MROWS * ND, cudaMemcpyDeviceToDevice);
    conv_pair<<<(MROWS * ND / 4 + 255) / 256, 256>>>((const float4*)hs, XH, XL, MROWS * ND / 4);

    for (int i = 0; i < NL; i++) {
        const size_t oDD = (size_t)i * WDD, oDF = (size_t)i * WDF, oCAT = (size_t)i * CATW;

        // fused q|k|c|v projection: [8192,768] @ [768,3072] -> PRJ pair
        gemm_tc<2, 256><<<dim3(12, 64, 1), 256, SM256_2>>>(
            XH, XL, 768, 0, 0, WCATH + oCAT, WCATL + oCAT, 768, 0, 0,
            nullptr, PRJH, PRJL, 3072, 0, 0, BCAT + i*4*ND, 3072, 768, 1, ID256);

        // V^T per head: PRJ cols [2304, 3072) -> VT pair [bh][64,512]
        transpose_pair<<<dim3(2, 16, NBH), tb>>>(PRJH + 3*ND, PRJL + 3*ND, SDP, NDH, NH,
                                                 VTH, VTL, VTS, 512, 64, 4*ND, 512);

        // score gram GEMMs (single K-chunk, 2 CTAs/SM)
        dim3 gS(2, 4, NBH);
        gemm_tc<0, 256><<<gS, 256, SM256_1>>>(
            PRJH + 2*ND, PRJL + 2*ND, 4*ND, SDP, NDH,
            PRJH + 2*ND, PRJL + 2*ND, 4*ND, SDP, NDH,
            S1, nullptr, nullptr, 512, HSS, SS, nullptr, 512, 64, NH, ID256);
        gemm_tc<0, 256><<<gS, 256, SM256_1>>>(
            PRJH + 0*ND, PRJL + 0*ND, 4*ND, SDP, NDH,
            PRJH + 1*ND, PRJL + 1*ND, 4*ND, SDP, NDH,
            S2, nullptr, nullptr, 512, HSS, SS, nullptr, 512, 64, NH, ID256);

        diag_rsqrt_kernel<<<(NBH * NS + 255) / 256, 256>>>(S1, CN);
        blend_softmax2<<<dim3(NS/8, NBH), 256>>>(S1, S2, CN, PH, PL);

        // ctx = P @ V^T
        gemm_tc<3, 64><<<dim3(1, 4, NBH), 256, SM64_2>>>(
            PH, PL, 512, HSS, SS, VTH, VTL, 512, (long long)NH * VTS, VTS,
            nullptr, CXH, CXL, 768, SD, NDH, nullptr, 64, 512, NH, ID64);

        // attn_out = LN(ctx @ Wo + bo + x)   [TN=128: 384 CTAs, better wave packing]
        gemm_tc<1, 128><<<dim3(6, 64, 1), 256, SM128_2>>>(
            CXH, CXL, 768, 0, 0, WOH + oDD, WOL + oDD, 768, 0, 0,
            TMP, nullptr, nullptr, 768, 0, 0, bo + i * ND, 768, 768, 1, ID128);
        add_ln_kernel<<<MROWS, 256>>>(TMP, XF, g1 + i * ND, b1 + i * ND, ATTF, ATH, ATL);

        // h = gelu(attn @ Wi + bi)
        gemm_tc<4, 256><<<dim3(12, 64, 1), 256, SM256_2>>>(
            ATH, ATL, 768, 0, 0, WIH + oDF, WIL + oDF, 768, 0, 0,
            nullptr, HH, HL, 3072, 0, 0, bi + i * NF, 3072, 768, 1, ID256);

        // x = LN(h @ Wo2 + bo2 + attn)   [TN=128: 384 CTAs, better wave packing]
        gemm_tc<1, 128><<<dim3(6, 64, 1), 256, SM128_2>>>(
            HH, HL, 3072, 0, 0, WO2H + oDF, WO2L + oDF, 3072, 0, 0,
            TMP, nullptr, nullptr, 768, 0, 0, bo2 + i * ND, 768, 3072, 1, ID128);
        add_ln_kernel<<<MROWS, 256>>>(TMP, ATTF, g2 + i * ND, b2 + i * ND, XF, XH, XL);
    }

    cudaMemcpyAsync(d_out, XF, sizeof(float) * MROWS * ND, cudaMemcpyDeviceToDevice);
}

// round 12
// speedup vs baseline: 1.2840x; 1.0235x over previous
#include <cuda_runtime.h>
#include <cuda_bf16.h>
#include <math.h>
#include <stdint.h>

#define NH 12
#define NB 16
#define NS 512
#define ND 768
#define NF 3072
#define NL 4
#define NDH 64
#define MROWS (NB*NS)      // 8192
#define NBH (NB*NH)        // 192

typedef __nv_bfloat16 bf16;

#if defined(__CUDA_ARCH_FEAT_SM103_ALL)
#define HAS_TC 1
#else
#define HAS_TC 0
#endif

// ---------------- scratch ----------------
__device__ float g_xf[MROWS*ND];
__device__ float g_tmp[MROWS*ND];
__device__ float g_attnf[MROWS*ND];
__device__ float g_s1[(size_t)NBH*NS*NS];
__device__ float g_s2[(size_t)NBH*NS*NS];
__device__ float g_cninv[NBH*NS];

__device__ bf16 g_xh[MROWS*ND],   g_xl[MROWS*ND];
__device__ bf16 g_prjh[(size_t)MROWS*4*ND], g_prjl[(size_t)MROWS*4*ND]; // q|k|c|v
__device__ bf16 g_ctxh[MROWS*ND], g_ctxl[MROWS*ND];
__device__ bf16 g_ath[MROWS*ND],  g_atl[MROWS*ND];
__device__ bf16 g_hh[(size_t)MROWS*NF], g_hl[(size_t)MROWS*NF];
__device__ bf16 g_ph[(size_t)NBH*NS*NS], g_pl[(size_t)NBH*NS*NS];
__device__ bf16 g_vth[NBH*NDH*NS], g_vtl[NBH*NDH*NS];

#define WDD (768*768)
#define WDF (768*3072)
#define CATW (4*WDD)
__device__ bf16 g_wcath[NL*CATW], g_wcatl[NL*CATW];
__device__ bf16 g_woh[NL*WDD], g_wol[NL*WDD];
__device__ bf16 g_wih[NL*WDF], g_wil[NL*WDF];
__device__ bf16 g_wo2h[NL*WDF], g_wo2l[NL*WDF];
__device__ float g_bcat[NL*4*ND];

// ---------------- helpers ----------------
__device__ __forceinline__ void split2(float v, bf16& h, bf16& l) {
    h = __float2bfloat16(v);
    l = __float2bfloat16(v - __bfloat162float(h));
}

__device__ __forceinline__ void cpa16(uint32_t dst, const void* src, int sz) {
    asm volatile("cp.async.cg.shared.global [%0], [%1], 16, %2;" :: "r"(dst), "l"(src), "r"(sz));
}

#define FENCE_PROXY_ASYNC() \
    asm volatile("fence.proxy.async.shared::cta;" ::: "memory")

#if HAS_TC
__device__ __forceinline__ uint32_t elect_one_pred() {
    uint32_t pred;
    asm volatile(
        "{\n\t.reg .pred p;\n\t"
        "elect.sync _|p, 0xFFFFFFFF;\n\t"
        "selp.b32 %0, 1, 0, p;\n\t}"
        : "=r"(pred));
    return pred;
}

static constexpr uint64_t SMEM_DESC_BASE_SW128 =
    (uint64_t(2) << 61) | (uint64_t(1) << 46) | (uint64_t(64) << 32) | (uint64_t(1) << 16);
#define MAKE_SMEM_DESC(base_addr) \
    (SMEM_DESC_BASE_SW128 | ((uint64_t)((base_addr) >> 4) & 0x3FFF))

#define TCGEN05_ALLOC(smem_result_addr, nCols) \
    asm volatile("tcgen05.alloc.cta_group::1.sync.aligned.shared::cta.b32 [%0], %1;" \
        :: "r"((uint32_t)(smem_result_addr)), "r"((uint32_t)(nCols)) : "memory")
#define TCGEN05_DEALLOC(tmem_addr, nCols) \
    asm volatile("tcgen05.dealloc.cta_group::1.sync.aligned.b32 %0, %1;" \
        :: "r"(tmem_addr), "r"((uint32_t)(nCols)))
#define TCGEN05_RELINQ() \
    asm volatile("tcgen05.relinquish_alloc_permit.cta_group::1.sync.aligned;")
#define TCGEN05_COMMIT(mbar) \
    asm volatile("tcgen05.commit.cta_group::1.mbarrier::arrive::one.shared::cluster.b64 [%0];" \
        :: "r"((uint32_t)(mbar)) : "memory")
#define TCGEN05_WAIT_LD() \
    asm volatile("tcgen05.wait::ld.sync.aligned;" ::: "memory")
#define TCGEN05_FENCE_AFTER() \
    asm volatile("tcgen05.fence::after_thread_sync;" ::: "memory")
#define TCGEN05_FENCE_BEFORE() \
    asm volatile("tcgen05.fence::before_thread_sync;" ::: "memory")

#define MBARRIER_INIT(mbar, count) \
    asm volatile("mbarrier.init.shared.b64 [%0], %1;" \
        :: "r"((uint32_t)(mbar)), "r"((uint32_t)(count)) : "memory")
#define MBARRIER_INVAL(mbar) \
    asm volatile("mbarrier.inval.shared.b64 [%0];" :: "r"((uint32_t)(mbar)) : "memory")
#define MBARRIER_WAIT_PARITY(mbar_addr, phase_parity) do { \
    uint32_t _mbar = (uint32_t)(mbar_addr); \
    uint32_t _parity = (uint32_t)(phase_parity); \
    uint32_t _done; \
    asm volatile( \
        "{\n\t.reg .pred p;\n\t" \
        "mbarrier.try_wait.parity.acquire.cta.shared::cta.b64 p, [%1], %2;\n\t" \
        "selp.b32 %0, 1, 0, p;\n\t}" \
        : "=r"(_done) : "r"(_mbar), "r"(_parity) : "memory"); \
    if (!_done) { \
        asm volatile( \
            "{\n\t.reg .pred P1;\n\t" \
            "WAIT_LOOP_%=:\n\t" \
            "mbarrier.try_wait.parity.acquire.cta.shared::cta.b64 P1, [%0], %1, 0x989680;\n\t" \
            "@P1 bra.uni WAIT_DONE_%=;\n\t" \
            "bra.uni WAIT_LOOP_%=;\n\t" \
            "WAIT_DONE_%=:\n\t}" \
            :: "r"(_mbar), "r"(_parity) : "memory"); \
    } \
} while(0)

#define TCGEN05_LD_32X32B_X32(r, tmem_addr) \
    asm volatile( \
        "tcgen05.ld.sync.aligned.32x32b.x32.b32 " \
        "{%0, %1, %2, %3, %4, %5, %6, %7, " \
        " %8, %9, %10, %11, %12, %13, %14, %15, " \
        " %16, %17, %18, %19, %20, %21, %22, %23, " \
        " %24, %25, %26, %27, %28, %29, %30, %31}, [%32];" \
        : "=r"((r)[0]),  "=r"((r)[1]),  "=r"((r)[2]),  "=r"((r)[3]), \
          "=r"((r)[4]),  "=r"((r)[5]),  "=r"((r)[6]),  "=r"((r)[7]), \
          "=r"((r)[8]),  "=r"((r)[9]),  "=r"((r)[10]), "=r"((r)[11]), \
          "=r"((r)[12]), "=r"((r)[13]), "=r"((r)[14]), "=r"((r)[15]), \
          "=r"((r)[16]), "=r"((r)[17]), "=r"((r)[18]), "=r"((r)[19]), \
          "=r"((r)[20]), "=r"((r)[21]), "=r"((r)[22]), "=r"((r)[23]), \
          "=r"((r)[24]), "=r"((r)[25]), "=r"((r)[26]), "=r"((r)[27]), \
          "=r"((r)[28]), "=r"((r)[29]), "=r"((r)[30]), "=r"((r)[31]) \
        : "r"(tmem_addr))

__device__ __forceinline__ void mma_f16_ss(uint32_t d, uint64_t ad, uint64_t bd,
                                           uint32_t idesc, uint32_t en) {
    asm volatile(
        "{\n\t.reg .pred p;\n\t"
        "setp.ne.u32 p, %5, 0;\n\t"
        "tcgen05.mma.cta_group::1.kind::f16 [%0], %1, %2, %3, {%4, %4, %4, %4}, p;\n\t}"
        :: "r"(d), "l"(ad), "l"(bd), "r"(idesc), "r"(0u), "r"(en) : "memory");
}
#endif

// ---------------- bf16x3 NT GEMM, TN-templated tile (128 x TN) ----------------
// EPI: 0 f32, 1 f32+bias, 2 pair+bias, 3 pair, 4 pair+bias+gelu, 7 f32+bias+residual
template<int EPI, int TN>
__global__ void __launch_bounds__(256) gemm_tc(
    const bf16* __restrict__ Ah_, const bf16* __restrict__ Al_,
    int lda, long long sAb, long long sAh,
    const bf16* __restrict__ Bh_, const bf16* __restrict__ Bl_,
    int ldb, long long sBb, long long sBh,
    float* __restrict__ Cf, bf16* __restrict__ Coh, bf16* __restrict__ Col,
    int ldc, long long sCb, long long sCh,
    const float* __restrict__ bias,
    int N, int K, int Hdiv, uint32_t idesc,
    const float* __restrict__ resid)
{
    constexpr int STAGE = (128 + TN) * 256;
    constexpr int AHOF = 0, ALOF = 16384, BHOF = 32768, BLOF = 32768 + TN * 128;
    extern __shared__ __align__(1024) char dsm[];
    const int tid = threadIdx.x, lane = tid & 31, wid = tid >> 5;
    const int zb = blockIdx.z / Hdiv, zh = blockIdx.z % Hdiv;
    const int m0 = blockIdx.y * 128, n0 = blockIdx.x * TN;
    const int nB = min(TN, N - n0);

    const bf16* Agh = Ah_ + zb*sAb + zh*sAh + (long long)m0 * lda;
    const bf16* Agl = Al_ + zb*sAb + zh*sAh + (long long)m0 * lda;
    const bf16* Bgh = Bh_ + zb*sBb + zh*sBh + (long long)n0 * ldb;
    const bf16* Bgl = Bl_ + zb*sBb + zh*sBh + (long long)n0 * ldb;

    float* Cfp = Cf  ? Cf  + zb*sCb + zh*sCh : nullptr;
    bf16*  Chp = Coh ? Coh + zb*sCb + zh*sCh : nullptr;
    bf16*  Clp = Col ? Col + zb*sCb + zh*sCh : nullptr;

#if HAS_TC
    const int nst = (K > 64) ? 2 : 1;
    uint32_t sb  = (uint32_t)__cvta_generic_to_shared(dsm);
    uint32_t ctl = sb + (uint32_t)(nst * STAGE);
    uint32_t mb0 = ctl + 8, mb1 = ctl + 16;

    if (tid == 0) { MBARRIER_INIT(mb0, 1); MBARRIER_INIT(mb1, 1); }
    if (wid == 4) { TCGEN05_ALLOC(ctl, TN); TCGEN05_RELINQ(); }
    __syncthreads();
    uint32_t tmem;
    asm volatile("ld.shared.b32 %0, [%1];" : "=r"(tmem) : "r"(ctl));

    const int KT = K >> 6;
    int ph0 = 0, ph1 = 0;

    auto issue = [&](int buf, int k0) {
        const uint32_t sbase = sb + (uint32_t)(buf * STAGE);
        constexpr int ITER = (128 + TN) * 8 / 256;
        #pragma unroll
        for (int i = 0; i < ITER; i++) {
            int id = tid + (i << 8);
            int row = id >> 3, cc = id & 7;
            if (row < 128) {
                uint32_t off = (uint32_t)((row << 7) + (cc << 4));
                uint32_t sw = off ^ ((off >> 3) & 0x70);
                long long ga = (long long)row * lda + k0 + (cc << 3);
                cpa16(sbase + AHOF + sw, Agh + ga, 16);
                cpa16(sbase + ALOF + sw, Agl + ga, 16);
            } else {
                int rb = row - 128;
                uint32_t off = (uint32_t)((rb << 7) + (cc << 4));
                uint32_t sw = off ^ ((off >> 3) & 0x70);
                int sz = 16, br = rb;
                if (rb >= nB) { sz = 0; br = 0; }
                long long gb = (long long)br * ldb + k0 + (cc << 3);
                cpa16(sbase + BHOF + sw, Bgh + gb, sz);
                cpa16(sbase + BLOF + sw, Bgl + gb, sz);
            }
        }
        asm volatile("cp.async.commit_group;");
    };

    issue(0, 0);
    for (int kt = 0; kt < KT; kt++) {
        const int buf = (nst == 2) ? (kt & 1) : 0;
        if (kt + 1 < KT) {
            if (kt >= 1) {
                if ((buf ^ 1) == 0) { MBARRIER_WAIT_PARITY(mb0, ph0); ph0 ^= 1; }
                else                { MBARRIER_WAIT_PARITY(mb1, ph1); ph1 ^= 1; }
            }
            issue(buf ^ 1, (kt + 1) << 6);
            asm volatile("cp.async.wait_group 1;");
        } else {
            asm volatile("cp.async.wait_group 0;");
        }
        FENCE_PROXY_ASYNC();
        __syncthreads();

        const uint32_t sbase = sb + (uint32_t)(buf * STAGE);
        if (wid == 4) {
            if (elect_one_pred()) {
                uint64_t dah = MAKE_SMEM_DESC(sbase + AHOF);
                uint64_t dal = MAKE_SMEM_DESC(sbase + ALOF);
                uint64_t dbh = MAKE_SMEM_DESC(sbase + BHOF);
                uint64_t dbl = MAKE_SMEM_DESC(sbase + BLOF);
                #pragma unroll
                for (int s = 0; s < 4; s++) {
                    uint32_t en0 = (kt == 0 && s == 0) ? 0u : 1u;
                    mma_f16_ss(tmem, dah + s*2, dbh + s*2, idesc, en0);
                    mma_f16_ss(tmem, dah + s*2, dbl + s*2, idesc, 1u);
                    mma_f16_ss(tmem, dal + s*2, dbh + s*2, idesc, 1u);
                }
                TCGEN05_COMMIT(buf ? mb1 : mb0);
            }
        }
        __syncthreads();
    }

    const int lastbuf = (nst == 2) ? ((KT - 1) & 1) : 0;
    if (lastbuf == 0) { MBARRIER_WAIT_PARITY(mb0, ph0); }
    else              { MBARRIER_WAIT_PARITY(mb1, ph1); }
    TCGEN05_FENCE_AFTER();

    // epilogue: TMEM -> SMEM pivot -> coalesced stores (R5/R8 proven)
    float* stg = (float*)dsm;
    for (int cb = 0; cb < nB; cb += 32) {
        if (wid < 4) {
            uint32_t d[32];
            TCGEN05_LD_32X32B_X32(d, tmem + cb);
            TCGEN05_WAIT_LD();
            int row = (wid << 5) + lane;
            #pragma unroll
            for (int j = 0; j < 32; j++) stg[row * 33 + j] = __uint_as_float(d[j]);
        }
        __syncthreads();
        #pragma unroll
        for (int it = 0; it < 4; it++) {
            int row = (it << 5) + (tid >> 3);
            int cc = (tid & 7) << 2;
            int gc = n0 + cb + cc;
            long long o = (long long)(m0 + row) * ldc + gc;
            float v[4];
            float4 rv;
            if (EPI == 7) rv = *(const float4*)(resid + o);
            #pragma unroll
            for (int j = 0; j < 4; j++) {
                v[j] = stg[row * 33 + cc + j];
                if (EPI == 1 || EPI == 2 || EPI == 4 || EPI == 7) v[j] += bias[gc + j];
                if (EPI == 7) v[j] += ((const float*)&rv)[j];
                if (EPI == 4) v[j] = 0.5f * v[j] * (1.0f + erff(v[j] * 0.70710678118654752f));
            }
            if (EPI <= 1 || EPI == 7) {
                *(float4*)(Cfp + o) = make_float4(v[0], v[1], v[2], v[3]);
            } else {
                bf16 h[4], l[4];
                #pragma unroll
                for (int j = 0; j < 4; j++) split2(v[j], h[j], l[j]);
                ((__nv_bfloat162*)(Chp + o))[0] = __nv_bfloat162(h[0], h[1]);
                ((__nv_bfloat162*)(Chp + o))[1] = __nv_bfloat162(h[2], h[3]);
                ((__nv_bfloat162*)(Clp + o))[0] = __nv_bfloat162(l[0], l[1]);
                ((__nv_bfloat162*)(Clp + o))[1] = __nv_bfloat162(l[2], l[3]);
            }
        }
        __syncthreads();
    }

    TCGEN05_FENCE_BEFORE();
    __syncthreads();
    if (tid == 0) { MBARRIER_INVAL(mb0); MBARRIER_INVAL(mb1); }
    if (wid == 4) TCGEN05_DEALLOC(tmem, TN);
#else
    // trivially-correct scalar fallback (never selected on sm_103a hardware)
    for (int o = tid; o < 128 * TN; o += 256) {
        int m = o / TN, n = o % TN;
        if (n >= nB) continue;
        float s = 0.f;
        const bf16* arh = Agh + (long long)m * lda;
        const bf16* arl = Agl + (long long)m * lda;
        const bf16* brh = Bgh + (long long)n * ldb;
        const bf16* brl = Bgl + (long long)n * ldb;
        for (int k = 0; k < K; k++)
            s += (__bfloat162float(arh[k]) + __bfloat162float(arl[k])) *
                 (__bfloat162float(brh[k]) + __bfloat162float(brl[k]));
        int gc = n0 + n;
        long long off = (long long)(m0 + m) * ldc + gc;
        if (EPI == 1 || EPI == 2 || EPI == 4 || EPI == 7) s += bias[gc];
        if (EPI == 7) s += resid[off];
        if (EPI == 4) s = 0.5f * s * (1.0f + erff(s * 0.70710678118654752f));
        if (EPI <= 1 || EPI == 7) Cfp[off] = s;
        else split2(s, Chp[off], Clp[off]);
    }
#endif
}

// ---------------- fp32 -> bf16 hi/lo split ----------------
__global__ void conv_pair(const float4* __restrict__ src, bf16* __restrict__ h,
                          bf16* __restrict__ l, int n4)
{
    int i = blockIdx.x * 256 + threadIdx.x;
    if (i < n4) {
        float4 v = src[i];
        int b = i * 4;
        split2(v.x, h[b], l[b]);
        split2(v.y, h[b + 1], l[b + 1]);
        split2(v.z, h[b + 2], l[b + 2]);
        split2(v.w, h[b + 3], l[b + 3]);
    }
}

// ---------------- gather concat bias: [bq|bk|bc|bv] per layer ----------------
__global__ void gather_bias(const float* __restrict__ bq, const float* __restrict__ bk,
                            const float* __restrict__ bc, const float* __restrict__ bv,
                            float* __restrict__ bcat)
{
    int i = blockIdx.x * 256 + threadIdx.x;      // 0 .. NL*4*ND
    int layer = i / (4 * ND), r = i % (4 * ND);
    int sect = r / ND, c = r % ND;
    const float* s = (sect == 0) ? bq : (sect == 1) ? bk : (sect == 2) ? bc : bv;
    bcat[i] = s[layer * ND + c];
}

// ---------------- transpose + split: fp32 [R,C] -> bf16 pair [C,R] ----------------
__global__ void transpose_split(const float* __restrict__ src, long long sS,
                                bf16* __restrict__ dh, bf16* __restrict__ dl, long long sD,
                                int R, int C, int lds, int ldd)
{
    __shared__ float t[32][33];
    const float* s = src + (long long)blockIdx.z * sS;
    bf16* oh = dh + (long long)blockIdx.z * sD;
    bf16* ol = dl + (long long)blockIdx.z * sD;
    int r0 = blockIdx.y * 32, c0 = blockIdx.x * 32;
    int tx = threadIdx.x, ty = threadIdx.y;
    #pragma unroll
    for (int i = 0; i < 4; i++) {
        int r = r0 + ty + i * 8;
        if (r < R && c0 + tx < C) t[ty + i * 8][tx] = s[(long long)r * lds + c0 + tx];
    }
    __syncthreads();
    #pragma unroll
    for (int i = 0; i < 4; i++) {
        int c = c0 + ty + i * 8, r = r0 + tx;
        if (c < C && r < R) {
            long long o = (long long)c * ldd + r;
            split2(t[tx][ty + i * 8], oh[o], ol[o]);
        }
    }
}

// ---------------- 4-weight batched transpose for WCAT (768x768 each) ----------------
__global__ void transpose_split4(const float* __restrict__ s0, const float* __restrict__ s1,
                                 const float* __restrict__ s2, const float* __restrict__ s3,
                                 bf16* __restrict__ dh, bf16* __restrict__ dl)
{
    __shared__ float t[32][33];
    int widx = blockIdx.z / NL, layer = blockIdx.z % NL;
    const float* s = ((widx == 0) ? s0 : (widx == 1) ? s1 : (widx == 2) ? s2 : s3)
                     + (long long)layer * WDD;
    bf16* oh = dh + (long long)layer * CATW + (long long)widx * WDD;
    bf16* ol = dl + (long long)layer * CATW + (long long)widx * WDD;
    int r0 = blockIdx.y * 32, c0 = blockIdx.x * 32;
    int tx = threadIdx.x, ty = threadIdx.y;
    #pragma unroll
    for (int i = 0; i < 4; i++) {
        int r = r0 + ty + i * 8;
        t[ty + i * 8][tx] = s[(long long)r * 768 + c0 + tx];
    }
    __syncthreads();
    #pragma unroll
    for (int i = 0; i < 4; i++) {
        int c = c0 + ty + i * 8, r = r0 + tx;
        long long o = (long long)c * 768 + r;
        split2(t[tx][ty + i * 8], oh[o], ol[o]);
    }
}

// ---------------- pair transpose: bf16 pair [R,C] -> bf16 pair [C,R] ----------------
__global__ void transpose_pair(const bf16* __restrict__ sh, const bf16* __restrict__ sl,
                               long long sSb, long long sSh, int Hdiv,
                               bf16* __restrict__ dh, bf16* __restrict__ dl, long long sD,
                               int R, int C, int lds, int ldd)
{
    __shared__ uint32_t t[32][33];
    int zb = blockIdx.z / Hdiv, zh = blockIdx.z % Hdiv;
    long long so = zb * sSb + zh * sSh;
    bf16* oh = dh + (long long)blockIdx.z * sD;
    bf16* ol = dl + (long long)blockIdx.z * sD;
    int r0 = blockIdx.y * 32, c0 = blockIdx.x * 32;
    int tx = threadIdx.x, ty = threadIdx.y;
    #pragma unroll
    for (int i = 0; i < 4; i++) {
        int r = r0 + ty + i * 8;
        if (r < R && c0 + tx < C) {
            long long a = so + (long long)r * lds + c0 + tx;
            uint16_t hv = __bfloat16_as_ushort(sh[a]);
            uint16_t lv = __bfloat16_as_ushort(sl[a]);
            t[ty + i * 8][tx] = (uint32_t)hv | ((uint32_t)lv << 16);
        }
    }
    __syncthreads();
    #pragma unroll
    for (int i = 0; i < 4; i++) {
        int c = c0 + ty + i * 8, r = r0 + tx;
        if (c < C && r < R) {
            long long o = (long long)c * ldd + r;
            uint32_t v = t[tx][ty + i * 8];
            oh[o] = __ushort_as_bfloat16((uint16_t)(v & 0xffff));
            ol[o] = __ushort_as_bfloat16((uint16_t)(v >> 16));
        }
    }
}

// ---------------- diag -> 1/||c|| ----------------
__global__ void diag_rsqrt_kernel(const float* __restrict__ Gc, float* __restrict__ cninv)
{
    int i = blockIdx.x * 256 + threadIdx.x;
    if (i < NBH * NS) {
        int bh = i / NS, s = i % NS;
        cninv[i] = rsqrtf(Gc[((long long)bh * NS + s) * NS + s]);
    }
}

// ---------------- blend + dual softmax: 1 warp per row ----------------
__global__ __launch_bounds__(256) void blend_softmax2(
    const float* __restrict__ Gc, const float* __restrict__ Gqk,
    const float* __restrict__ cninv, bf16* __restrict__ ph, bf16* __restrict__ pl)
{
    const int lane = threadIdx.x & 31, wid = threadIdx.x >> 5;
    const int row = blockIdx.x * 8 + wid;
    const int bh = blockIdx.y;
    const long long base = ((long long)bh * NS + row) * NS;
    const float4* gc4 = (const float4*)(Gc + base);
    const float4* gq4 = (const float4*)(Gqk + base);
    const float4* cn4 = (const float4*)(cninv + bh * NS);
    const float cl = cninv[bh * NS + row];

    float s1[16], s2[16];
    #pragma unroll
    for (int j = 0; j < 4; j++) {
        int idx = j * 32 + lane;
        float4 g = gc4[idx];
        float4 q = gq4[idx];
        float4 cr = cn4[idx];
        int c0 = idx * 4;
        s1[j*4+0] = 1.0f - g.x * cl * cr.x + (c0     == row ? 1.0f : 0.0f);
        s1[j*4+1] = 1.0f - g.y * cl * cr.y + (c0 + 1 == row ? 1.0f : 0.0f);
        s1[j*4+2] = 1.0f - g.z * cl * cr.z + (c0 + 2 == row ? 1.0f : 0.0f);
        s1[j*4+3] = 1.0f - g.w * cl * cr.w + (c0 + 3 == row ? 1.0f : 0.0f);
        s2[j*4+0] = q.x * 0.125f;
        s2[j*4+1] = q.y * 0.125f;
        s2[j*4+2] = q.z * 0.125f;
        s2[j*4+3] = q.w * 0.125f;
    }
    float m1 = -1e30f, m2 = -1e30f;
    #pragma unroll
    for (int j = 0; j < 16; j++) { m1 = fmaxf(m1, s1[j]); m2 = fmaxf(m2, s2[j]); }
    #pragma unroll
    for (int o = 16; o; o >>= 1) {
        m1 = fmaxf(m1, __shfl_xor_sync(0xffffffffu, m1, o));
        m2 = fmaxf(m2, __shfl_xor_sync(0xffffffffu, m2, o));
    }
    float sum1 = 0.f, sum2 = 0.f;
    #pragma unroll
    for (int j = 0; j < 16; j++) {
        s1[j] = __expf(s1[j] - m1); sum1 += s1[j];
        s2[j] = __expf(s2[j] - m2); sum2 += s2[j];
    }
    #pragma unroll
    for (int o = 16; o; o >>= 1) {
        sum1 += __shfl_xor_sync(0xffffffffu, sum1, o);
        sum2 += __shfl_xor_sync(0xffffffffu, sum2, o);
    }
    float inv1 = 0.5f / sum1, inv2 = 0.5f / sum2;
    #pragma unroll
    for (int j = 0; j < 4; j++) {
        int c0 = (j * 32 + lane) * 4;
        __nv_bfloat162 h2[2], l2[2];
        #pragma unroll
        for (int e = 0; e < 4; e++) {
            float p = s1[j*4+e] * inv1 + s2[j*4+e] * inv2;
            bf16 h, l;
            split2(p, h, l);
            ((bf16*)h2)[e] = h;
            ((bf16*)l2)[e] = l;
        }
        *(uint2*)(ph + base + c0) = *(uint2*)h2;
        *(uint2*)(pl + base + c0) = *(uint2*)l2;
    }
}

// ---------------- LayerNorm, warp-per-row (input already includes residual) ----------------
__global__ __launch_bounds__(256) void ln_warp(
    const float* __restrict__ inp,
    const float* __restrict__ g, const float* __restrict__ b,
    float* __restrict__ outf, bf16* __restrict__ outh, bf16* __restrict__ outl)
{
    const int lane = threadIdx.x & 31, wid = threadIdx.x >> 5;
    const long long row = (long long)blockIdx.x * 8 + wid;
    const float4* ip4 = (const float4*)(inp + row * ND);

    float4 v[6];
    float s = 0.f;
    #pragma unroll
    for (int j = 0; j < 6; j++) {
        v[j] = ip4[j * 32 + lane];
        s += v[j].x + v[j].y + v[j].z + v[j].w;
    }
    #pragma unroll
    for (int o = 16; o; o >>= 1) s += __shfl_xor_sync(0xffffffffu, s, o);
    const float mu = s * (1.0f / ND);

    float q = 0.f;
    #pragma unroll
    for (int j = 0; j < 6; j++) {
        float a0 = v[j].x - mu, a1 = v[j].y - mu, a2 = v[j].z - mu, a3 = v[j].w - mu;
        q += a0*a0 + a1*a1 + a2*a2 + a3*a3;
    }
    #pragma unroll
    for (int o = 16; o; o >>= 1) q += __shfl_xor_sync(0xffffffffu, q, o);
    const float inv = rsqrtf(q * (1.0f / ND) + 1e-12f);

    #pragma unroll
    for (int j = 0; j < 6; j++) {
        int c = (j * 32 + lane) * 4;
        long long o = row * ND + c;
        float4 gg = *(const float4*)(g + c);
        float4 bb = *(const float4*)(b + c);
        float r0 = (v[j].x - mu) * inv * gg.x + bb.x;
        float r1 = (v[j].y - mu) * inv * gg.y + bb.y;
        float r2 = (v[j].z - mu) * inv * gg.z + bb.z;
        float r3 = (v[j].w - mu) * inv * gg.w + bb.w;
        *(float4*)(outf + o) = make_float4(r0, r1, r2, r3);
        __nv_bfloat162 h2[2], l2[2];
        bf16 h, l;
        split2(r0, h, l); h2[0].x = h; l2[0].x = l;
        split2(r1, h, l); h2[0].y = h; l2[0].y = l;
        split2(r2, h, l); h2[1].x = h; l2[1].x = l;
        split2(r3, h, l); h2[1].y = h; l2[1].y = l;
        *(uint2*)(outh + o) = *(uint2*)h2;
        *(uint2*)(outl + o) = *(uint2*)l2;
    }
}

// ---------------- host ----------------
static float* symf(const void* s) { void* p = nullptr; cudaGetSymbolAddress(&p, s); return (float*)p; }
static bf16*  symb(const void* s) { void* p = nullptr; cudaGetSymbolAddress(&p, s); return (bf16*)p; }

#define SMEMSZ(TN, nst) ((nst) * ((128 + (TN)) * 256) + 64)

extern "C" void kernel_launch(void* const* d_in, const int* in_sizes, int n_in,
                              void* d_out, int out_size)
{
    const float* hs  = (const float*)d_in[0];
    const float* Wq  = (const float*)d_in[1];  const float* bq  = (const float*)d_in[2];
    const float* Wk  = (const float*)d_in[3];  const float* bk  = (const float*)d_in[4];
    const float* Wv  = (const float*)d_in[5];  const float* bv  = (const float*)d_in[6];
    const float* Wc  = (const float*)d_in[7];  const float* bc  = (const float*)d_in[8];
    const float* Wo  = (const float*)d_in[9];  const float* bo  = (const float*)d_in[10];
    const float* g1  = (const float*)d_in[11]; const float* b1  = (const float*)d_in[12];
    const float* Wi  = (const float*)d_in[13]; const float* bi  = (const float*)d_in[14];
    const float* Wo2 = (const float*)d_in[15]; const float* bo2 = (const float*)d_in[16];
    const float* g2  = (const float*)d_in[17]; const float* b2  = (const float*)d_in[18];

    const int SM256_2 = SMEMSZ(256, 2);
    const int SM256_1 = SMEMSZ(256, 1);
    const int SM128_2 = SMEMSZ(128, 2);
    const int SM64_2  = SMEMSZ(64, 2);

    cudaFuncSetAttribute(gemm_tc<0, 256>, cudaFuncAttributeMaxDynamicSharedMemorySize, SM256_2);
    cudaFuncSetAttribute(gemm_tc<7, 128>, cudaFuncAttributeMaxDynamicSharedMemorySize, SM128_2);
    cudaFuncSetAttribute(gemm_tc<2, 256>, cudaFuncAttributeMaxDynamicSharedMemorySize, SM256_2);
    cudaFuncSetAttribute(gemm_tc<4, 256>, cudaFuncAttributeMaxDynamicSharedMemorySize, SM256_2);
    cudaFuncSetAttribute(gemm_tc<3, 64>,  cudaFuncAttributeMaxDynamicSharedMemorySize, SM64_2);

    float* XF   = symf(g_xf);
    float* TMP  = symf(g_tmp);
    float* ATTF = symf(g_attnf);
    float* S1   = symf(g_s1);
    float* S2   = symf(g_s2);
    float* CN   = symf(g_cninv);
    float* BCAT = symf(g_bcat);

    bf16 *XH = symb(g_xh), *XL = symb(g_xl);
    bf16 *PRJH = symb(g_prjh), *PRJL = symb(g_prjl);
    bf16 *CXH = symb(g_ctxh), *CXL = symb(g_ctxl);
    bf16 *ATH = symb(g_ath), *ATL = symb(g_atl);
    bf16 *HH = symb(g_hh), *HL = symb(g_hl);
    bf16 *PH = symb(g_ph), *PL = symb(g_pl);
    bf16 *VTH = symb(g_vth), *VTL = symb(g_vtl);

    bf16 *WCATH = symb(g_wcath), *WCATL = symb(g_wcatl);
    bf16 *WOH = symb(g_woh), *WOL = symb(g_wol);
    bf16 *WIH = symb(g_wih), *WIL = symb(g_wil);
    bf16 *WO2H = symb(g_wo2h), *WO2L = symb(g_wo2l);

    const long long SD   = (long long)NS * ND;
    const long long SDP  = (long long)NS * (4 * ND);
    const long long SS   = (long long)NS * NS;
    const long long HSS  = (long long)NH * SS;
    const long long VTS  = (long long)NDH * NS;

    const uint32_t ID256 = 0x8000490u | (32u << 17);
    const uint32_t ID128 = 0x8000490u | (16u << 17);
    const uint32_t ID64  = 0x8000490u | (8u << 17);

    dim3 tb(32, 8);

    // --- launch order tuned so kernel launch #5 is the first score GEMM ---
    // #0
    conv_pair<<<(MROWS * ND / 4 + 255) / 256, 256>>>((const float4*)hs, XH, XL, MROWS * ND / 4);
    // #1
    gather_bias<<<(NL * 4 * ND) / 256, 256>>>(bq, bk, bc, bv, BCAT);
    // #2: all 4 projection weights transposed in one launch
    transpose_split4<<<dim3(24, 24, 4 * NL), tb>>>(Wq, Wk, Wc, Wv, WCATH, WCATL);
    cudaMemcpyAsync(XF, hs, sizeof(float) * MROWS * ND, cudaMemcpyDeviceToDevice);

    bool late_t = false;   // Wo/Wi/Wo2 transposes issued after first scores
    for (int i = 0; i < NL; i++) {
        const size_t oDD = (size_t)i * WDD, oDF = (size_t)i * WDF, oCAT = (size_t)i * CATW;

        // #3: fused q|k|c|v projection
        gemm_tc<2, 256><<<dim3(12, 64, 1), 256, SM256_2>>>(
            XH, XL, 768, 0, 0, WCATH + oCAT, WCATL + oCAT, 768, 0, 0,
            nullptr, PRJH, PRJL, 3072, 0, 0, BCAT + i*4*ND, 3072, 768, 1, ID256, nullptr);

        // #4: V^T per head
        transpose_pair<<<dim3(2, 16, NBH), tb>>>(PRJH + 3*ND, PRJL + 3*ND, SDP, NDH, NH,
                                                 VTH, VTL, VTS, 512, 64, 4*ND, 512);

        // #5 / #6: score gram GEMMs  (ncu -s 5 lands on S1)
        dim3 gS(2, 4, NBH);
        gemm_tc<0, 256><<<gS, 256, SM256_1>>>(
            PRJH + 2*ND, PRJL + 2*ND, 4*ND, SDP, NDH,
            PRJH + 2*ND, PRJL + 2*ND, 4*ND, SDP, NDH,
            S1, nullptr, nullptr, 512, HSS, SS, nullptr, 512, 64, NH, ID256, nullptr);
        gemm_tc<0, 256><<<gS, 256, SM256_1>>>(
            PRJH + 0*ND, PRJL + 0*ND, 4*ND, SDP, NDH,
            PRJH + 1*ND, PRJL + 1*ND, 4*ND, SDP, NDH,
            S2, nullptr, nullptr, 512, HSS, SS, nullptr, 512, 64, NH, ID256, nullptr);

        if (!late_t) {
            // remaining weight transposes (input-only deps; deferred past the scores)
            transpose_split<<<dim3(24, 24, NL), tb>>>(Wo,  WDD, WOH,  WOL,  WDD, 768, 768, 768, 768);
            transpose_split<<<dim3(96, 24, NL), tb>>>(Wi,  WDF, WIH,  WIL,  WDF, 768, 3072, 3072, 768);
            transpose_split<<<dim3(24, 96, NL), tb>>>(Wo2, WDF, WO2H, WO2L, WDF, 3072, 768, 768, 3072);
            late_t = true;
        }

        diag_rsqrt_kernel<<<(NBH * NS + 255) / 256, 256>>>(S1, CN);
        blend_softmax2<<<dim3(NS/8, NBH), 256>>>(S1, S2, CN, PH, PL);

        // ctx = P @ V^T
        gemm_tc<3, 64><<<dim3(1, 4, NBH), 256, SM64_2>>>(
            PH, PL, 512, HSS, SS, VTH, VTL, 512, (long long)NH * VTS, VTS,
            nullptr, CXH, CXL, 768, SD, NDH, nullptr, 64, 512, NH, ID64, nullptr);

        // TMP = ctx @ Wo + bo + x   (residual fused); then LN
        gemm_tc<7, 128><<<dim3(6, 64, 1), 256, SM128_2>>>(
            CXH, CXL, 768, 0, 0, WOH + oDD, WOL + oDD, 768, 0, 0,
            TMP, nullptr, nullptr, 768, 0, 0, bo + i * ND, 768, 768, 1, ID128, XF);
        ln_warp<<<MROWS / 8, 256>>>(TMP, g1 + i * ND, b1 + i * ND, ATTF, ATH, ATL);

        // h = gelu(attn @ Wi + bi)
        gemm_tc<4, 256><<<dim3(12, 64, 1), 256, SM256_2>>>(
            ATH, ATL, 768, 0, 0, WIH + oDF, WIL + oDF, 768, 0, 0,
            nullptr, HH, HL, 3072, 0, 0, bi + i * NF, 3072, 768, 1, ID256, nullptr);

        // TMP = h @ Wo2 + bo2 + attn  (residual fused); then LN -> x
        gemm_tc<7, 128><<<dim3(6, 64, 1), 256, SM128_2>>>(
            HH, HL, 3072, 0, 0, WO2H + oDF, WO2L + oDF, 3072, 0, 0,
            TMP, nullptr, nullptr, 768, 0, 0, bo2 + i * ND, 768, 3072, 1, ID128, ATTF);
        ln_warp<<<MROWS / 8, 256>>>(TMP, g2 + i * ND, b2 + i * ND, XF, XH, XL);
    }

    cudaMemcpyAsync(d_out, XF, sizeof(float) * MROWS * ND, cudaMemcpyDeviceToDevice);
}

// round 13
// speedup vs baseline: 1.5475x; 1.2052x over previous
#include <cuda_runtime.h>
#include <cuda_bf16.h>
#include <math.h>
#include <stdint.h>

#define NH 12
#define NB 16
#define NS 512
#define ND 768
#define NF 3072
#define NL 4
#define NDH 64
#define MROWS (NB*NS)      // 8192
#define NBH (NB*NH)        // 192

typedef __nv_bfloat16 bf16;

#if defined(__CUDA_ARCH_FEAT_SM103_ALL)
#define HAS_TC 1
#else
#define HAS_TC 0
#endif

// ---------------- scratch ----------------
__device__ float g_xf[MROWS*ND];
__device__ float g_tmp[MROWS*ND];
__device__ float g_attnf[MROWS*ND];
__device__ float g_s1[(size_t)NBH*NS*NS];
__device__ float g_s2[(size_t)NBH*NS*NS];
__device__ float g_cninv[NBH*NS];

__device__ bf16 g_xh[MROWS*ND],   g_xl[MROWS*ND];
__device__ bf16 g_prjh[(size_t)MROWS*4*ND], g_prjl[(size_t)MROWS*4*ND]; // q|k|c|v
__device__ bf16 g_ctxh[MROWS*ND], g_ctxl[MROWS*ND];
__device__ bf16 g_ath[MROWS*ND],  g_atl[MROWS*ND];
__device__ bf16 g_hh[(size_t)MROWS*NF], g_hl[(size_t)MROWS*NF];
__device__ bf16 g_ph[(size_t)NBH*NS*NS], g_pl[(size_t)NBH*NS*NS];
__device__ bf16 g_vth[NBH*NDH*NS], g_vtl[NBH*NDH*NS];

#define WDD (768*768)
#define WDF (768*3072)
#define CATW (4*WDD)
__device__ bf16 g_wcath[NL*CATW], g_wcatl[NL*CATW];
__device__ bf16 g_woh[NL*WDD], g_wol[NL*WDD];
__device__ bf16 g_wih[NL*WDF], g_wil[NL*WDF];
__device__ bf16 g_wo2h[NL*WDF], g_wo2l[NL*WDF];
__device__ float g_bcat[NL*4*ND];

// ---------------- helpers ----------------
__device__ __forceinline__ void split2(float v, bf16& h, bf16& l) {
    h = __float2bfloat16(v);
    l = __float2bfloat16(v - __bfloat162float(h));
}

__device__ __forceinline__ void cpa16(uint32_t dst, const void* src, int sz) {
    asm volatile("cp.async.cg.shared.global [%0], [%1], 16, %2;" :: "r"(dst), "l"(src), "r"(sz));
}

#define FENCE_PROXY_ASYNC() \
    asm volatile("fence.proxy.async.shared::cta;" ::: "memory")

#if HAS_TC
__device__ __forceinline__ uint32_t elect_one_pred() {
    uint32_t pred;
    asm volatile(
        "{\n\t.reg .pred p;\n\t"
        "elect.sync _|p, 0xFFFFFFFF;\n\t"
        "selp.b32 %0, 1, 0, p;\n\t}"
        : "=r"(pred));
    return pred;
}

static constexpr uint64_t SMEM_DESC_BASE_SW128 =
    (uint64_t(2) << 61) | (uint64_t(1) << 46) | (uint64_t(64) << 32) | (uint64_t(1) << 16);
#define MAKE_SMEM_DESC(base_addr) \
    (SMEM_DESC_BASE_SW128 | ((uint64_t)((base_addr) >> 4) & 0x3FFF))

#define TCGEN05_ALLOC(smem_result_addr, nCols) \
    asm volatile("tcgen05.alloc.cta_group::1.sync.aligned.shared::cta.b32 [%0], %1;" \
        :: "r"((uint32_t)(smem_result_addr)), "r"((uint32_t)(nCols)) : "memory")
#define TCGEN05_DEALLOC(tmem_addr, nCols) \
    asm volatile("tcgen05.dealloc.cta_group::1.sync.aligned.b32 %0, %1;" \
        :: "r"(tmem_addr), "r"((uint32_t)(nCols)))
#define TCGEN05_RELINQ() \
    asm volatile("tcgen05.relinquish_alloc_permit.cta_group::1.sync.aligned;")
#define TCGEN05_COMMIT(mbar) \
    asm volatile("tcgen05.commit.cta_group::1.mbarrier::arrive::one.shared::cluster.b64 [%0];" \
        :: "r"((uint32_t)(mbar)) : "memory")
#define TCGEN05_WAIT_LD() \
    asm volatile("tcgen05.wait::ld.sync.aligned;" ::: "memory")
#define TCGEN05_FENCE_AFTER() \
    asm volatile("tcgen05.fence::after_thread_sync;" ::: "memory")
#define TCGEN05_FENCE_BEFORE() \
    asm volatile("tcgen05.fence::before_thread_sync;" ::: "memory")

#define MBARRIER_INIT(mbar, count) \
    asm volatile("mbarrier.init.shared.b64 [%0], %1;" \
        :: "r"((uint32_t)(mbar)), "r"((uint32_t)(count)) : "memory")
#define MBARRIER_INVAL(mbar) \
    asm volatile("mbarrier.inval.shared.b64 [%0];" :: "r"((uint32_t)(mbar)) : "memory")
#define MBARRIER_WAIT_PARITY(mbar_addr, phase_parity) do { \
    uint32_t _mbar = (uint32_t)(mbar_addr); \
    uint32_t _parity = (uint32_t)(phase_parity); \
    uint32_t _done; \
    asm volatile( \
        "{\n\t.reg .pred p;\n\t" \
        "mbarrier.try_wait.parity.acquire.cta.shared::cta.b64 p, [%1], %2;\n\t" \
        "selp.b32 %0, 1, 0, p;\n\t}" \
        : "=r"(_done) : "r"(_mbar), "r"(_parity) : "memory"); \
    if (!_done) { \
        asm volatile( \
            "{\n\t.reg .pred P1;\n\t" \
            "WAIT_LOOP_%=:\n\t" \
            "mbarrier.try_wait.parity.acquire.cta.shared::cta.b64 P1, [%0], %1, 0x989680;\n\t" \
            "@P1 bra.uni WAIT_DONE_%=;\n\t" \
            "bra.uni WAIT_LOOP_%=;\n\t" \
            "WAIT_DONE_%=:\n\t}" \
            :: "r"(_mbar), "r"(_parity) : "memory"); \
    } \
} while(0)

#define TCGEN05_LD_32X32B_X32(r, tmem_addr) \
    asm volatile( \
        "tcgen05.ld.sync.aligned.32x32b.x32.b32 " \
        "{%0, %1, %2, %3, %4, %5, %6, %7, " \
        " %8, %9, %10, %11, %12, %13, %14, %15, " \
        " %16, %17, %18, %19, %20, %21, %22, %23, " \
        " %24, %25, %26, %27, %28, %29, %30, %31}, [%32];" \
        : "=r"((r)[0]),  "=r"((r)[1]),  "=r"((r)[2]),  "=r"((r)[3]), \
          "=r"((r)[4]),  "=r"((r)[5]),  "=r"((r)[6]),  "=r"((r)[7]), \
          "=r"((r)[8]),  "=r"((r)[9]),  "=r"((r)[10]), "=r"((r)[11]), \
          "=r"((r)[12]), "=r"((r)[13]), "=r"((r)[14]), "=r"((r)[15]), \
          "=r"((r)[16]), "=r"((r)[17]), "=r"((r)[18]), "=r"((r)[19]), \
          "=r"((r)[20]), "=r"((r)[21]), "=r"((r)[22]), "=r"((r)[23]), \
          "=r"((r)[24]), "=r"((r)[25]), "=r"((r)[26]), "=r"((r)[27]), \
          "=r"((r)[28]), "=r"((r)[29]), "=r"((r)[30]), "=r"((r)[31]) \
        : "r"(tmem_addr))

__device__ __forceinline__ void mma_f16_ss(uint32_t d, uint64_t ad, uint64_t bd,
                                           uint32_t idesc, uint32_t en) {
    asm volatile(
        "{\n\t.reg .pred p;\n\t"
        "setp.ne.u32 p, %5, 0;\n\t"
        "tcgen05.mma.cta_group::1.kind::f16 [%0], %1, %2, %3, {%4, %4, %4, %4}, p;\n\t}"
        :: "r"(d), "l"(ad), "l"(bd), "r"(idesc), "r"(0u), "r"(en) : "memory");
}
#endif

// ---------------- bf16x3 NT GEMM, (128 x TN) tile, NST-stage pipeline ----------------
// EPI: 0 f32, 1 f32+bias, 2 pair+bias, 3 pair, 4 pair+bias+gelu, 7 f32+bias+residual
// NST=1: single buffer, serial load->MMA per chunk; relies on co-resident CTAs for overlap.
// NST=2: classic double buffer.
template<int EPI, int TN, int NST>
__global__ void __launch_bounds__(256) gemm_tc(
    const bf16* __restrict__ Ah_, const bf16* __restrict__ Al_,
    int lda, long long sAb, long long sAh,
    const bf16* __restrict__ Bh_, const bf16* __restrict__ Bl_,
    int ldb, long long sBb, long long sBh,
    float* __restrict__ Cf, bf16* __restrict__ Coh, bf16* __restrict__ Col,
    int ldc, long long sCb, long long sCh,
    const float* __restrict__ bias,
    int N, int K, int Hdiv, uint32_t idesc,
    const float* __restrict__ resid)
{
    constexpr int STAGE = (128 + TN) * 256;
    constexpr int AHOF = 0, ALOF = 16384, BHOF = 32768, BLOF = 32768 + TN * 128;
    extern __shared__ __align__(1024) char dsm[];
    const int tid = threadIdx.x, lane = tid & 31, wid = tid >> 5;
    const int zb = blockIdx.z / Hdiv, zh = blockIdx.z % Hdiv;
    const int m0 = blockIdx.y * 128, n0 = blockIdx.x * TN;
    const int nB = min(TN, N - n0);

    const bf16* Agh = Ah_ + zb*sAb + zh*sAh + (long long)m0 * lda;
    const bf16* Agl = Al_ + zb*sAb + zh*sAh + (long long)m0 * lda;
    const bf16* Bgh = Bh_ + zb*sBb + zh*sBh + (long long)n0 * ldb;
    const bf16* Bgl = Bl_ + zb*sBb + zh*sBh + (long long)n0 * ldb;

    float* Cfp = Cf  ? Cf  + zb*sCb + zh*sCh : nullptr;
    bf16*  Chp = Coh ? Coh + zb*sCb + zh*sCh : nullptr;
    bf16*  Clp = Col ? Col + zb*sCb + zh*sCh : nullptr;

#if HAS_TC
    uint32_t sb  = (uint32_t)__cvta_generic_to_shared(dsm);
    uint32_t ctl = sb + (uint32_t)(NST * STAGE);
    uint32_t mb0 = ctl + 8, mb1 = ctl + 16;

    if (tid == 0) { MBARRIER_INIT(mb0, 1); MBARRIER_INIT(mb1, 1); }
    if (wid == 4) { TCGEN05_ALLOC(ctl, TN); TCGEN05_RELINQ(); }
    __syncthreads();
    uint32_t tmem;
    asm volatile("ld.shared.b32 %0, [%1];" : "=r"(tmem) : "r"(ctl));

    const int KT = K >> 6;
    int ph0 = 0, ph1 = 0;

    auto issue = [&](int buf, int k0) {
        const uint32_t sbase = sb + (uint32_t)(buf * STAGE);
        constexpr int ITER = (128 + TN) * 8 / 256;
        #pragma unroll
        for (int i = 0; i < ITER; i++) {
            int id = tid + (i << 8);
            int row = id >> 3, cc = id & 7;
            if (row < 128) {
                uint32_t off = (uint32_t)((row << 7) + (cc << 4));
                uint32_t sw = off ^ ((off >> 3) & 0x70);
                long long ga = (long long)row * lda + k0 + (cc << 3);
                cpa16(sbase + AHOF + sw, Agh + ga, 16);
                cpa16(sbase + ALOF + sw, Agl + ga, 16);
            } else {
                int rb = row - 128;
                uint32_t off = (uint32_t)((rb << 7) + (cc << 4));
                uint32_t sw = off ^ ((off >> 3) & 0x70);
                int sz = 16, br = rb;
                if (rb >= nB) { sz = 0; br = 0; }
                long long gb = (long long)br * ldb + k0 + (cc << 3);
                cpa16(sbase + BHOF + sw, Bgh + gb, sz);
                cpa16(sbase + BLOF + sw, Bgl + gb, sz);
            }
        }
        asm volatile("cp.async.commit_group;");
    };

    // issue MMAs for one chunk from a stage
    auto mma_chunk = [&](int buf, int kt) {
        if (wid == 4) {
            if (elect_one_pred()) {
                const uint32_t sbase = sb + (uint32_t)(buf * STAGE);
                uint64_t dah = MAKE_SMEM_DESC(sbase + AHOF);
                uint64_t dal = MAKE_SMEM_DESC(sbase + ALOF);
                uint64_t dbh = MAKE_SMEM_DESC(sbase + BHOF);
                uint64_t dbl = MAKE_SMEM_DESC(sbase + BLOF);
                #pragma unroll
                for (int s = 0; s < 4; s++) {
                    uint32_t en0 = (kt == 0 && s == 0) ? 0u : 1u;
                    mma_f16_ss(tmem, dah + s*2, dbh + s*2, idesc, en0);
                    mma_f16_ss(tmem, dah + s*2, dbl + s*2, idesc, 1u);
                    mma_f16_ss(tmem, dal + s*2, dbh + s*2, idesc, 1u);
                }
                TCGEN05_COMMIT(buf ? mb1 : mb0);
            }
        }
    };

    issue(0, 0);
    if (NST == 2) {
        for (int kt = 0; kt < KT; kt++) {
            const int buf = kt & 1;
            if (kt + 1 < KT) {
                if (kt >= 1) {
                    if ((buf ^ 1) == 0) { MBARRIER_WAIT_PARITY(mb0, ph0); ph0 ^= 1; }
                    else                { MBARRIER_WAIT_PARITY(mb1, ph1); ph1 ^= 1; }
                }
                issue(buf ^ 1, (kt + 1) << 6);
                asm volatile("cp.async.wait_group 1;");
            } else {
                asm volatile("cp.async.wait_group 0;");
            }
            FENCE_PROXY_ASYNC();
            __syncthreads();
            mma_chunk(buf, kt);
            __syncthreads();
        }
        const int lastbuf = (KT - 1) & 1;
        if (lastbuf == 0) { MBARRIER_WAIT_PARITY(mb0, ph0); }
        else              { MBARRIER_WAIT_PARITY(mb1, ph1); }
    } else {
        // single-stage: serial per chunk; co-resident CTAs provide overlap
        for (int kt = 0; kt < KT; kt++) {
            asm volatile("cp.async.wait_group 0;");
            FENCE_PROXY_ASYNC();
            __syncthreads();
            mma_chunk(0, kt);
            __syncthreads();
            if (kt + 1 < KT) {
                MBARRIER_WAIT_PARITY(mb0, ph0); ph0 ^= 1;
                issue(0, (kt + 1) << 6);
            }
        }
        MBARRIER_WAIT_PARITY(mb0, ph0);
    }
    TCGEN05_FENCE_AFTER();

    // epilogue: TMEM -> SMEM pivot -> coalesced stores (R5/R8 proven)
    float* stg = (float*)dsm;
    for (int cb = 0; cb < nB; cb += 32) {
        if (wid < 4) {
            uint32_t d[32];
            TCGEN05_LD_32X32B_X32(d, tmem + cb);
            TCGEN05_WAIT_LD();
            int row = (wid << 5) + lane;
            #pragma unroll
            for (int j = 0; j < 32; j++) stg[row * 33 + j] = __uint_as_float(d[j]);
        }
        __syncthreads();
        #pragma unroll
        for (int it = 0; it < 4; it++) {
            int row = (it << 5) + (tid >> 3);
            int cc = (tid & 7) << 2;
            int gc = n0 + cb + cc;
            long long o = (long long)(m0 + row) * ldc + gc;
            float v[4];
            float4 rv;
            if (EPI == 7) rv = *(const float4*)(resid + o);
            #pragma unroll
            for (int j = 0; j < 4; j++) {
                v[j] = stg[row * 33 + cc + j];
                if (EPI == 1 || EPI == 2 || EPI == 4 || EPI == 7) v[j] += bias[gc + j];
                if (EPI == 7) v[j] += ((const float*)&rv)[j];
                if (EPI == 4) v[j] = 0.5f * v[j] * (1.0f + erff(v[j] * 0.70710678118654752f));
            }
            if (EPI <= 1 || EPI == 7) {
                *(float4*)(Cfp + o) = make_float4(v[0], v[1], v[2], v[3]);
            } else {
                bf16 h[4], l[4];
                #pragma unroll
                for (int j = 0; j < 4; j++) split2(v[j], h[j], l[j]);
                ((__nv_bfloat162*)(Chp + o))[0] = __nv_bfloat162(h[0], h[1]);
                ((__nv_bfloat162*)(Chp + o))[1] = __nv_bfloat162(h[2], h[3]);
                ((__nv_bfloat162*)(Clp + o))[0] = __nv_bfloat162(l[0], l[1]);
                ((__nv_bfloat162*)(Clp + o))[1] = __nv_bfloat162(l[2], l[3]);
            }
        }
        __syncthreads();
    }

    TCGEN05_FENCE_BEFORE();
    __syncthreads();
    if (tid == 0) { MBARRIER_INVAL(mb0); MBARRIER_INVAL(mb1); }
    if (wid == 4) TCGEN05_DEALLOC(tmem, TN);
#else
    // trivially-correct scalar fallback (never selected on sm_103a hardware)
    for (int o = tid; o < 128 * TN; o += 256) {
        int m = o / TN, n = o % TN;
        if (n >= nB) continue;
        float s = 0.f;
        const bf16* arh = Agh + (long long)m * lda;
        const bf16* arl = Agl + (long long)m * lda;
        const bf16* brh = Bgh + (long long)n * ldb;
        const bf16* brl = Bgl + (long long)n * ldb;
        for (int k = 0; k < K; k++)
            s += (__bfloat162float(arh[k]) + __bfloat162float(arl[k])) *
                 (__bfloat162float(brh[k]) + __bfloat162float(brl[k]));
        int gc = n0 + n;
        long long off = (long long)(m0 + m) * ldc + gc;
        if (EPI == 1 || EPI == 2 || EPI == 4 || EPI == 7) s += bias[gc];
        if (EPI == 7) s += resid[off];
        if (EPI == 4) s = 0.5f * s * (1.0f + erff(s * 0.70710678118654752f));
        if (EPI <= 1 || EPI == 7) Cfp[off] = s;
        else split2(s, Chp[off], Clp[off]);
    }
#endif
}

// ---------------- fp32 -> bf16 hi/lo split ----------------
__global__ void conv_pair(const float4* __restrict__ src, bf16* __restrict__ h,
                          bf16* __restrict__ l, int n4)
{
    int i = blockIdx.x * 256 + threadIdx.x;
    if (i < n4) {
        float4 v = src[i];
        int b = i * 4;
        split2(v.x, h[b], l[b]);
        split2(v.y, h[b + 1], l[b + 1]);
        split2(v.z, h[b + 2], l[b + 2]);
        split2(v.w, h[b + 3], l[b + 3]);
    }
}

// ---------------- gather concat bias ----------------
__global__ void gather_bias(const float* __restrict__ bq, const float* __restrict__ bk,
                            const float* __restrict__ bc, const float* __restrict__ bv,
                            float* __restrict__ bcat)
{
    int i = blockIdx.x * 256 + threadIdx.x;
    int layer = i / (4 * ND), r = i % (4 * ND);
    int sect = r / ND, c = r % ND;
    const float* s = (sect == 0) ? bq : (sect == 1) ? bk : (sect == 2) ? bc : bv;
    bcat[i] = s[layer * ND + c];
}

// ---------------- transpose + split ----------------
__global__ void transpose_split(const float* __restrict__ src, long long sS,
                                bf16* __restrict__ dh, bf16* __restrict__ dl, long long sD,
                                int R, int C, int lds, int ldd)
{
    __shared__ float t[32][33];
    const float* s = src + (long long)blockIdx.z * sS;
    bf16* oh = dh + (long long)blockIdx.z * sD;
    bf16* ol = dl + (long long)blockIdx.z * sD;
    int r0 = blockIdx.y * 32, c0 = blockIdx.x * 32;
    int tx = threadIdx.x, ty = threadIdx.y;
    #pragma unroll
    for (int i = 0; i < 4; i++) {
        int r = r0 + ty + i * 8;
        if (r < R && c0 + tx < C) t[ty + i * 8][tx] = s[(long long)r * lds + c0 + tx];
    }
    __syncthreads();
    #pragma unroll
    for (int i = 0; i < 4; i++) {
        int c = c0 + ty + i * 8, r = r0 + tx;
        if (c < C && r < R) {
            long long o = (long long)c * ldd + r;
            split2(t[tx][ty + i * 8], oh[o], ol[o]);
        }
    }
}

// ---------------- 4-weight batched transpose for WCAT ----------------
__global__ void transpose_split4(const float* __restrict__ s0, const float* __restrict__ s1,
                                 const float* __restrict__ s2, const float* __restrict__ s3,
                                 bf16* __restrict__ dh, bf16* __restrict__ dl)
{
    __shared__ float t[32][33];
    int widx = blockIdx.z / NL, layer = blockIdx.z % NL;
    const float* s = ((widx == 0) ? s0 : (widx == 1) ? s1 : (widx == 2) ? s2 : s3)
                     + (long long)layer * WDD;
    bf16* oh = dh + (long long)layer * CATW + (long long)widx * WDD;
    bf16* ol = dl + (long long)layer * CATW + (long long)widx * WDD;
    int r0 = blockIdx.y * 32, c0 = blockIdx.x * 32;
    int tx = threadIdx.x, ty = threadIdx.y;
    #pragma unroll
    for (int i = 0; i < 4; i++) {
        int r = r0 + ty + i * 8;
        t[ty + i * 8][tx] = s[(long long)r * 768 + c0 + tx];
    }
    __syncthreads();
    #pragma unroll
    for (int i = 0; i < 4; i++) {
        int c = c0 + ty + i * 8, r = r0 + tx;
        long long o = (long long)c * 768 + r;
        split2(t[tx][ty + i * 8], oh[o], ol[o]);
    }
}

// ---------------- pair transpose ----------------
__global__ void transpose_pair(const bf16* __restrict__ sh, const bf16* __restrict__ sl,
                               long long sSb, long long sSh, int Hdiv,
                               bf16* __restrict__ dh, bf16* __restrict__ dl, long long sD,
                               int R, int C, int lds, int ldd)
{
    __shared__ uint32_t t[32][33];
    int zb = blockIdx.z / Hdiv, zh = blockIdx.z % Hdiv;
    long long so = zb * sSb + zh * sSh;
    bf16* oh = dh + (long long)blockIdx.z * sD;
    bf16* ol = dl + (long long)blockIdx.z * sD;
    int r0 = blockIdx.y * 32, c0 = blockIdx.x * 32;
    int tx = threadIdx.x, ty = threadIdx.y;
    #pragma unroll
    for (int i = 0; i < 4; i++) {
        int r = r0 + ty + i * 8;
        if (r < R && c0 + tx < C) {
            long long a = so + (long long)r * lds + c0 + tx;
            uint16_t hv = __bfloat16_as_ushort(sh[a]);
            uint16_t lv = __bfloat16_as_ushort(sl[a]);
            t[ty + i * 8][tx] = (uint32_t)hv | ((uint32_t)lv << 16);
        }
    }
    __syncthreads();
    #pragma unroll
    for (int i = 0; i < 4; i++) {
        int c = c0 + ty + i * 8, r = r0 + tx;
        if (c < C && r < R) {
            long long o = (long long)c * ldd + r;
            uint32_t v = t[tx][ty + i * 8];
            oh[o] = __ushort_as_bfloat16((uint16_t)(v & 0xffff));
            ol[o] = __ushort_as_bfloat16((uint16_t)(v >> 16));
        }
    }
}

// ---------------- diag -> 1/||c|| ----------------
__global__ void diag_rsqrt_kernel(const float* __restrict__ Gc, float* __restrict__ cninv)
{
    int i = blockIdx.x * 256 + threadIdx.x;
    if (i < NBH * NS) {
        int bh = i / NS, s = i % NS;
        cninv[i] = rsqrtf(Gc[((long long)bh * NS + s) * NS + s]);
    }
}

// ---------------- blend + dual softmax: 1 warp per row ----------------
__global__ __launch_bounds__(256) void blend_softmax2(
    const float* __restrict__ Gc, const float* __restrict__ Gqk,
    const float* __restrict__ cninv, bf16* __restrict__ ph, bf16* __restrict__ pl)
{
    const int lane = threadIdx.x & 31, wid = threadIdx.x >> 5;
    const int row = blockIdx.x * 8 + wid;
    const int bh = blockIdx.y;
    const long long base = ((long long)bh * NS + row) * NS;
    const float4* gc4 = (const float4*)(Gc + base);
    const float4* gq4 = (const float4*)(Gqk + base);
    const float4* cn4 = (const float4*)(cninv + bh * NS);
    const float cl = cninv[bh * NS + row];

    float s1[16], s2[16];
    #pragma unroll
    for (int j = 0; j < 4; j++) {
        int idx = j * 32 + lane;
        float4 g = gc4[idx];
        float4 q = gq4[idx];
        float4 cr = cn4[idx];
        int c0 = idx * 4;
        s1[j*4+0] = 1.0f - g.x * cl * cr.x + (c0     == row ? 1.0f : 0.0f);
        s1[j*4+1] = 1.0f - g.y * cl * cr.y + (c0 + 1 == row ? 1.0f : 0.0f);
        s1[j*4+2] = 1.0f - g.z * cl * cr.z + (c0 + 2 == row ? 1.0f : 0.0f);
        s1[j*4+3] = 1.0f - g.w * cl * cr.w + (c0 + 3 == row ? 1.0f : 0.0f);
        s2[j*4+0] = q.x * 0.125f;
        s2[j*4+1] = q.y * 0.125f;
        s2[j*4+2] = q.z * 0.125f;
        s2[j*4+3] = q.w * 0.125f;
    }
    float m1 = -1e30f, m2 = -1e30f;
    #pragma unroll
    for (int j = 0; j < 16; j++) { m1 = fmaxf(m1, s1[j]); m2 = fmaxf(m2, s2[j]); }
    #pragma unroll
    for (int o = 16; o; o >>= 1) {
        m1 = fmaxf(m1, __shfl_xor_sync(0xffffffffu, m1, o));
        m2 = fmaxf(m2, __shfl_xor_sync(0xffffffffu, m2, o));
    }
    float sum1 = 0.f, sum2 = 0.f;
    #pragma unroll
    for (int j = 0; j < 16; j++) {
        s1[j] = __expf(s1[j] - m1); sum1 += s1[j];
        s2[j] = __expf(s2[j] - m2); sum2 += s2[j];
    }
    #pragma unroll
    for (int o = 16; o; o >>= 1) {
        sum1 += __shfl_xor_sync(0xffffffffu, sum1, o);
        sum2 += __shfl_xor_sync(0xffffffffu, sum2, o);
    }
    float inv1 = 0.5f / sum1, inv2 = 0.5f / sum2;
    #pragma unroll
    for (int j = 0; j < 4; j++) {
        int c0 = (j * 32 + lane) * 4;
        __nv_bfloat162 h2[2], l2[2];
        #pragma unroll
        for (int e = 0; e < 4; e++) {
            float p = s1[j*4+e] * inv1 + s2[j*4+e] * inv2;
            bf16 h, l;
            split2(p, h, l);
            ((bf16*)h2)[e] = h;
            ((bf16*)l2)[e] = l;
        }
        *(uint2*)(ph + base + c0) = *(uint2*)h2;
        *(uint2*)(pl + base + c0) = *(uint2*)l2;
    }
}

// ---------------- LayerNorm, warp-per-row ----------------
__global__ __launch_bounds__(256) void ln_warp(
    const float* __restrict__ inp,
    const float* __restrict__ g, const float* __restrict__ b,
    float* __restrict__ outf, bf16* __restrict__ outh, bf16* __restrict__ outl)
{
    const int lane = threadIdx.x & 31, wid = threadIdx.x >> 5;
    const long long row = (long long)blockIdx.x * 8 + wid;
    const float4* ip4 = (const float4*)(inp + row * ND);

    float4 v[6];
    float s = 0.f;
    #pragma unroll
    for (int j = 0; j < 6; j++) {
        v[j] = ip4[j * 32 + lane];
        s += v[j].x + v[j].y + v[j].z + v[j].w;
    }
    #pragma unroll
    for (int o = 16; o; o >>= 1) s += __shfl_xor_sync(0xffffffffu, s, o);
    const float mu = s * (1.0f / ND);

    float q = 0.f;
    #pragma unroll
    for (int j = 0; j < 6; j++) {
        float a0 = v[j].x - mu, a1 = v[j].y - mu, a2 = v[j].z - mu, a3 = v[j].w - mu;
        q += a0*a0 + a1*a1 + a2*a2 + a3*a3;
    }
    #pragma unroll
    for (int o = 16; o; o >>= 1) q += __shfl_xor_sync(0xffffffffu, q, o);
    const float inv = rsqrtf(q * (1.0f / ND) + 1e-12f);

    #pragma unroll
    for (int j = 0; j < 6; j++) {
        int c = (j * 32 + lane) * 4;
        long long o = row * ND + c;
        float4 gg = *(const float4*)(g + c);
        float4 bb = *(const float4*)(b + c);
        float r0 = (v[j].x - mu) * inv * gg.x + bb.x;
        float r1 = (v[j].y - mu) * inv * gg.y + bb.y;
        float r2 = (v[j].z - mu) * inv * gg.z + bb.z;
        float r3 = (v[j].w - mu) * inv * gg.w + bb.w;
        *(float4*)(outf + o) = make_float4(r0, r1, r2, r3);
        __nv_bfloat162 h2[2], l2[2];
        bf16 h, l;
        split2(r0, h, l); h2[0].x = h; l2[0].x = l;
        split2(r1, h, l); h2[0].y = h; l2[0].y = l;
        split2(r2, h, l); h2[1].x = h; l2[1].x = l;
        split2(r3, h, l); h2[1].y = h; l2[1].y = l;
        *(uint2*)(outh + o) = *(uint2*)h2;
        *(uint2*)(outl + o) = *(uint2*)l2;
    }
}

// ---------------- host ----------------
static float* symf(const void* s) { void* p = nullptr; cudaGetSymbolAddress(&p, s); return (float*)p; }
static bf16*  symb(const void* s) { void* p = nullptr; cudaGetSymbolAddress(&p, s); return (bf16*)p; }

#define SMEMSZ(TN, nst) ((nst) * ((128 + (TN)) * 256) + 64)

extern "C" void kernel_launch(void* const* d_in, const int* in_sizes, int n_in,
                              void* d_out, int out_size)
{
    const float* hs  = (const float*)d_in[0];
    const float* Wq  = (const float*)d_in[1];  const float* bq  = (const float*)d_in[2];
    const float* Wk  = (const float*)d_in[3];  const float* bk  = (const float*)d_in[4];
    const float* Wv  = (const float*)d_in[5];  const float* bv  = (const float*)d_in[6];
    const float* Wc  = (const float*)d_in[7];  const float* bc  = (const float*)d_in[8];
    const float* Wo  = (const float*)d_in[9];  const float* bo  = (const float*)d_in[10];
    const float* g1  = (const float*)d_in[11]; const float* b1  = (const float*)d_in[12];
    const float* Wi  = (const float*)d_in[13]; const float* bi  = (const float*)d_in[14];
    const float* Wo2 = (const float*)d_in[15]; const float* bo2 = (const float*)d_in[16];
    const float* g2  = (const float*)d_in[17]; const float* b2  = (const float*)d_in[18];

    const int SM256_1 = SMEMSZ(256, 1);   // 98368  -> 2 CTAs/SM
    const int SM128_1 = SMEMSZ(128, 1);   // 65600  -> 3 CTAs/SM
    const int SM64_2  = SMEMSZ(64, 2);    // 98368  -> 2 CTAs/SM

    cudaFuncSetAttribute(gemm_tc<0, 256, 1>, cudaFuncAttributeMaxDynamicSharedMemorySize, SM256_1);
    cudaFuncSetAttribute(gemm_tc<2, 256, 1>, cudaFuncAttributeMaxDynamicSharedMemorySize, SM256_1);
    cudaFuncSetAttribute(gemm_tc<4, 256, 1>, cudaFuncAttributeMaxDynamicSharedMemorySize, SM256_1);
    cudaFuncSetAttribute(gemm_tc<7, 128, 1>, cudaFuncAttributeMaxDynamicSharedMemorySize, SM128_1);
    cudaFuncSetAttribute(gemm_tc<3, 64, 2>,  cudaFuncAttributeMaxDynamicSharedMemorySize, SM64_2);

    float* XF   = symf(g_xf);
    float* TMP  = symf(g_tmp);
    float* ATTF = symf(g_attnf);
    float* S1   = symf(g_s1);
    float* S2   = symf(g_s2);
    float* CN   = symf(g_cninv);
    float* BCAT = symf(g_bcat);

    bf16 *XH = symb(g_xh), *XL = symb(g_xl);
    bf16 *PRJH = symb(g_prjh), *PRJL = symb(g_prjl);
    bf16 *CXH = symb(g_ctxh), *CXL = symb(g_ctxl);
    bf16 *ATH = symb(g_ath), *ATL = symb(g_atl);
    bf16 *HH = symb(g_hh), *HL = symb(g_hl);
    bf16 *PH = symb(g_ph), *PL = symb(g_pl);
    bf16 *VTH = symb(g_vth), *VTL = symb(g_vtl);

    bf16 *WCATH = symb(g_wcath), *WCATL = symb(g_wcatl);
    bf16 *WOH = symb(g_woh), *WOL = symb(g_wol);
    bf16 *WIH = symb(g_wih), *WIL = symb(g_wil);
    bf16 *WO2H = symb(g_wo2h), *WO2L = symb(g_wo2l);

    const long long SD   = (long long)NS * ND;
    const long long SDP  = (long long)NS * (4 * ND);
    const long long SS   = (long long)NS * NS;
    const long long HSS  = (long long)NH * SS;
    const long long VTS  = (long long)NDH * NS;

    const uint32_t ID256 = 0x8000490u | (32u << 17);
    const uint32_t ID128 = 0x8000490u | (16u << 17);
    const uint32_t ID64  = 0x8000490u | (8u << 17);

    dim3 tb(32, 8);

    conv_pair<<<(MROWS * ND / 4 + 255) / 256, 256>>>((const float4*)hs, XH, XL, MROWS * ND / 4);
    gather_bias<<<(NL * 4 * ND) / 256, 256>>>(bq, bk, bc, bv, BCAT);
    transpose_split4<<<dim3(24, 24, 4 * NL), tb>>>(Wq, Wk, Wc, Wv, WCATH, WCATL);
    cudaMemcpyAsync(XF, hs, sizeof(float) * MROWS * ND, cudaMemcpyDeviceToDevice);

    bool late_t = false;
    for (int i = 0; i < NL; i++) {
        const size_t oDD = (size_t)i * WDD, oDF = (size_t)i * WDF, oCAT = (size_t)i * CATW;

        // fused q|k|c|v projection (1-stage, 2 CTAs/SM)
        gemm_tc<2, 256, 1><<<dim3(12, 64, 1), 256, SM256_1>>>(
            XH, XL, 768, 0, 0, WCATH + oCAT, WCATL + oCAT, 768, 0, 0,
            nullptr, PRJH, PRJL, 3072, 0, 0, BCAT + i*4*ND, 3072, 768, 1, ID256, nullptr);

        // V^T per head
        transpose_pair<<<dim3(2, 16, NBH), tb>>>(PRJH + 3*ND, PRJL + 3*ND, SDP, NDH, NH,
                                                 VTH, VTL, VTS, 512, 64, 4*ND, 512);

        // score gram GEMMs (1-stage, KT==1, 2 CTAs/SM) — launch #5 for ncu
        dim3 gS(2, 4, NBH);
        gemm_tc<0, 256, 1><<<gS, 256, SM256_1>>>(
            PRJH + 2*ND, PRJL + 2*ND, 4*ND, SDP, NDH,
            PRJH + 2*ND, PRJL + 2*ND, 4*ND, SDP, NDH,
            S1, nullptr, nullptr, 512, HSS, SS, nullptr, 512, 64, NH, ID256, nullptr);
        gemm_tc<0, 256, 1><<<gS, 256, SM256_1>>>(
            PRJH + 0*ND, PRJL + 0*ND, 4*ND, SDP, NDH,
            PRJH + 1*ND, PRJL + 1*ND, 4*ND, SDP, NDH,
            S2, nullptr, nullptr, 512, HSS, SS, nullptr, 512, 64, NH, ID256, nullptr);

        if (!late_t) {
            transpose_split<<<dim3(24, 24, NL), tb>>>(Wo,  WDD, WOH,  WOL,  WDD, 768, 768, 768, 768);
            transpose_split<<<dim3(96, 24, NL), tb>>>(Wi,  WDF, WIH,  WIL,  WDF, 768, 3072, 3072, 768);
            transpose_split<<<dim3(24, 96, NL), tb>>>(Wo2, WDF, WO2H, WO2L, WDF, 3072, 768, 768, 3072);
            late_t = true;
        }

        diag_rsqrt_kernel<<<(NBH * NS + 255) / 256, 256>>>(S1, CN);
        blend_softmax2<<<dim3(NS/8, NBH), 256>>>(S1, S2, CN, PH, PL);

        // ctx = P @ V^T (2-stage TN=64, proven)
        gemm_tc<3, 64, 2><<<dim3(1, 4, NBH), 256, SM64_2>>>(
            PH, PL, 512, HSS, SS, VTH, VTL, 512, (long long)NH * VTS, VTS,
            nullptr, CXH, CXL, 768, SD, NDH, nullptr, 64, 512, NH, ID64, nullptr);

        // TMP = ctx @ Wo + bo + x (1-stage TN=128, 3 CTAs/SM); then LN
        gemm_tc<7, 128, 1><<<dim3(6, 64, 1), 256, SM128_1>>>(
            CXH, CXL, 768, 0, 0, WOH + oDD, WOL + oDD, 768, 0, 0,
            TMP, nullptr, nullptr, 768, 0, 0, bo + i * ND, 768, 768, 1, ID128, XF);
        ln_warp<<<MROWS / 8, 256>>>(TMP, g1 + i * ND, b1 + i * ND, ATTF, ATH, ATL);

        // h = gelu(attn @ Wi + bi) (1-stage, 2 CTAs/SM)
        gemm_tc<4, 256, 1><<<dim3(12, 64, 1), 256, SM256_1>>>(
            ATH, ATL, 768, 0, 0, WIH + oDF, WIL + oDF, 768, 0, 0,
            nullptr, HH, HL, 3072, 0, 0, bi + i * NF, 3072, 768, 1, ID256, nullptr);

        // TMP = h @ Wo2 + bo2 + attn (1-stage TN=128); then LN -> x
        gemm_tc<7, 128, 1><<<dim3(6, 64, 1), 256, SM128_1>>>(
            HH, HL, 3072, 0, 0, WO2H + oDF, WO2L + oDF, 3072, 0, 0,
            TMP, nullptr, nullptr, 768, 0, 0, bo2 + i * ND, 768, 3072, 1, ID128, ATTF);
        ln_warp<<<MROWS / 8, 256>>>(TMP, g2 + i * ND, b2 + i * ND, XF, XH, XL);
    }

    cudaMemcpyAsync(d_out, XF, sizeof(float) * MROWS * ND, cudaMemcpyDeviceToDevice);
}

// round 14
// speedup vs baseline: 1.5754x; 1.0181x over previous
#include <cuda_runtime.h>
#include <cuda_bf16.h>
#include <math.h>
#include <stdint.h>

#define NH 12
#define NB 16
#define NS 512
#define ND 768
#define NF 3072
#define NL 4
#define NDH 64
#define MROWS (NB*NS)      // 8192
#define NBH (NB*NH)        // 192

typedef __nv_bfloat16 bf16;

#if defined(__CUDA_ARCH_FEAT_SM103_ALL)
#define HAS_TC 1
#else
#define HAS_TC 0
#endif

// ---------------- scratch ----------------
__device__ float g_xf[MROWS*ND];
__device__ float g_tmp[MROWS*ND];
__device__ float g_attnf[MROWS*ND];
__device__ float g_s1[(size_t)NBH*NS*NS];
__device__ float g_s2[(size_t)NBH*NS*NS];
__device__ float g_cninv[NBH*NS];

__device__ bf16 g_xh[MROWS*ND],   g_xl[MROWS*ND];
__device__ bf16 g_prjh[(size_t)MROWS*4*ND], g_prjl[(size_t)MROWS*4*ND]; // q|k|c|v
__device__ bf16 g_ctxh[MROWS*ND], g_ctxl[MROWS*ND];
__device__ bf16 g_ath[MROWS*ND],  g_atl[MROWS*ND];
__device__ bf16 g_hh[(size_t)MROWS*NF], g_hl[(size_t)MROWS*NF];
__device__ bf16 g_ph[(size_t)NBH*NS*NS], g_pl[(size_t)NBH*NS*NS];
__device__ bf16 g_vth[NBH*NDH*NS], g_vtl[NBH*NDH*NS];

#define WDD (768*768)
#define WDF (768*3072)
#define CATW (4*WDD)
__device__ bf16 g_wcath[NL*CATW], g_wcatl[NL*CATW];
__device__ bf16 g_woh[NL*WDD], g_wol[NL*WDD];
__device__ bf16 g_wih[NL*WDF], g_wil[NL*WDF];
__device__ bf16 g_wo2h[NL*WDF], g_wo2l[NL*WDF];
__device__ float g_bcat[NL*4*ND];

// ---------------- helpers ----------------
__device__ __forceinline__ void split2(float v, bf16& h, bf16& l) {
    h = __float2bfloat16(v);
    l = __float2bfloat16(v - __bfloat162float(h));
}

__device__ __forceinline__ void cpa16(uint32_t dst, const void* src, int sz) {
    asm volatile("cp.async.cg.shared.global [%0], [%1], 16, %2;" :: "r"(dst), "l"(src), "r"(sz));
}

#define FENCE_PROXY_ASYNC() \
    asm volatile("fence.proxy.async.shared::cta;" ::: "memory")

#if HAS_TC
__device__ __forceinline__ uint32_t elect_one_pred() {
    uint32_t pred;
    asm volatile(
        "{\n\t.reg .pred p;\n\t"
        "elect.sync _|p, 0xFFFFFFFF;\n\t"
        "selp.b32 %0, 1, 0, p;\n\t}"
        : "=r"(pred));
    return pred;
}

static constexpr uint64_t SMEM_DESC_BASE_SW128 =
    (uint64_t(2) << 61) | (uint64_t(1) << 46) | (uint64_t(64) << 32) | (uint64_t(1) << 16);
#define MAKE_SMEM_DESC(base_addr) \
    (SMEM_DESC_BASE_SW128 | ((uint64_t)((base_addr) >> 4) & 0x3FFF))

#define TCGEN05_ALLOC(smem_result_addr, nCols) \
    asm volatile("tcgen05.alloc.cta_group::1.sync.aligned.shared::cta.b32 [%0], %1;" \
        :: "r"((uint32_t)(smem_result_addr)), "r"((uint32_t)(nCols)) : "memory")
#define TCGEN05_DEALLOC(tmem_addr, nCols) \
    asm volatile("tcgen05.dealloc.cta_group::1.sync.aligned.b32 %0, %1;" \
        :: "r"(tmem_addr), "r"((uint32_t)(nCols)))
#define TCGEN05_RELINQ() \
    asm volatile("tcgen05.relinquish_alloc_permit.cta_group::1.sync.aligned;")
#define TCGEN05_COMMIT(mbar) \
    asm volatile("tcgen05.commit.cta_group::1.mbarrier::arrive::one.shared::cluster.b64 [%0];" \
        :: "r"((uint32_t)(mbar)) : "memory")
#define TCGEN05_WAIT_LD() \
    asm volatile("tcgen05.wait::ld.sync.aligned;" ::: "memory")
#define TCGEN05_FENCE_AFTER() \
    asm volatile("tcgen05.fence::after_thread_sync;" ::: "memory")
#define TCGEN05_FENCE_BEFORE() \
    asm volatile("tcgen05.fence::before_thread_sync;" ::: "memory")

#define MBARRIER_INIT(mbar, count) \
    asm volatile("mbarrier.init.shared.b64 [%0], %1;" \
        :: "r"((uint32_t)(mbar)), "r"((uint32_t)(count)) : "memory")
#define MBARRIER_INVAL(mbar) \
    asm volatile("mbarrier.inval.shared.b64 [%0];" :: "r"((uint32_t)(mbar)) : "memory")
#define MBARRIER_WAIT_PARITY(mbar_addr, phase_parity) do { \
    uint32_t _mbar = (uint32_t)(mbar_addr); \
    uint32_t _parity = (uint32_t)(phase_parity); \
    uint32_t _done; \
    asm volatile( \
        "{\n\t.reg .pred p;\n\t" \
        "mbarrier.try_wait.parity.acquire.cta.shared::cta.b64 p, [%1], %2;\n\t" \
        "selp.b32 %0, 1, 0, p;\n\t}" \
        : "=r"(_done) : "r"(_mbar), "r"(_parity) : "memory"); \
    if (!_done) { \
        asm volatile( \
            "{\n\t.reg .pred P1;\n\t" \
            "WAIT_LOOP_%=:\n\t" \
            "mbarrier.try_wait.parity.acquire.cta.shared::cta.b64 P1, [%0], %1, 0x989680;\n\t" \
            "@P1 bra.uni WAIT_DONE_%=;\n\t" \
            "bra.uni WAIT_LOOP_%=;\n\t" \
            "WAIT_DONE_%=:\n\t}" \
            :: "r"(_mbar), "r"(_parity) : "memory"); \
    } \
} while(0)

#define TCGEN05_LD_32X32B_X32(r, tmem_addr) \
    asm volatile( \
        "tcgen05.ld.sync.aligned.32x32b.x32.b32 " \
        "{%0, %1, %2, %3, %4, %5, %6, %7, " \
        " %8, %9, %10, %11, %12, %13, %14, %15, " \
        " %16, %17, %18, %19, %20, %21, %22, %23, " \
        " %24, %25, %26, %27, %28, %29, %30, %31}, [%32];" \
        : "=r"((r)[0]),  "=r"((r)[1]),  "=r"((r)[2]),  "=r"((r)[3]), \
          "=r"((r)[4]),  "=r"((r)[5]),  "=r"((r)[6]),  "=r"((r)[7]), \
          "=r"((r)[8]),  "=r"((r)[9]),  "=r"((r)[10]), "=r"((r)[11]), \
          "=r"((r)[12]), "=r"((r)[13]), "=r"((r)[14]), "=r"((r)[15]), \
          "=r"((r)[16]), "=r"((r)[17]), "=r"((r)[18]), "=r"((r)[19]), \
          "=r"((r)[20]), "=r"((r)[21]), "=r"((r)[22]), "=r"((r)[23]), \
          "=r"((r)[24]), "=r"((r)[25]), "=r"((r)[26]), "=r"((r)[27]), \
          "=r"((r)[28]), "=r"((r)[29]), "=r"((r)[30]), "=r"((r)[31]) \
        : "r"(tmem_addr))

__device__ __forceinline__ void mma_f16_ss(uint32_t d, uint64_t ad, uint64_t bd,
                                           uint32_t idesc, uint32_t en) {
    asm volatile(
        "{\n\t.reg .pred p;\n\t"
        "setp.ne.u32 p, %5, 0;\n\t"
        "tcgen05.mma.cta_group::1.kind::f16 [%0], %1, %2, %3, {%4, %4, %4, %4}, p;\n\t}"
        :: "r"(d), "l"(ad), "l"(bd), "r"(idesc), "r"(0u), "r"(en) : "memory");
}
#endif

// ---------------- bf16x3 NT GEMM, (128 x TN) tile, NST-stage pipeline ----------------
// EPI: 0 f32, 1 f32+bias, 2 pair+bias, 3 pair, 4 pair+bias+gelu, 7 f32+bias+residual
// NST=1: single buffer, serial load->MMA per chunk; co-resident CTAs provide overlap.
// NST=2: classic double buffer.
template<int EPI, int TN, int NST>
__global__ void __launch_bounds__(256) gemm_tc(
    const bf16* __restrict__ Ah_, const bf16* __restrict__ Al_,
    int lda, long long sAb, long long sAh,
    const bf16* __restrict__ Bh_, const bf16* __restrict__ Bl_,
    int ldb, long long sBb, long long sBh,
    float* __restrict__ Cf, bf16* __restrict__ Coh, bf16* __restrict__ Col,
    int ldc, long long sCb, long long sCh,
    const float* __restrict__ bias,
    int N, int K, int Hdiv, uint32_t idesc,
    const float* __restrict__ resid)
{
    constexpr int STAGE = (128 + TN) * 256;
    constexpr int AHOF = 0, ALOF = 16384, BHOF = 32768, BLOF = 32768 + TN * 128;
    extern __shared__ __align__(1024) char dsm[];
    const int tid = threadIdx.x, lane = tid & 31, wid = tid >> 5;
    const int zb = blockIdx.z / Hdiv, zh = blockIdx.z % Hdiv;
    const int m0 = blockIdx.y * 128, n0 = blockIdx.x * TN;
    const int nB = min(TN, N - n0);

    const bf16* Agh = Ah_ + zb*sAb + zh*sAh + (long long)m0 * lda;
    const bf16* Agl = Al_ + zb*sAb + zh*sAh + (long long)m0 * lda;
    const bf16* Bgh = Bh_ + zb*sBb + zh*sBh + (long long)n0 * ldb;
    const bf16* Bgl = Bl_ + zb*sBb + zh*sBh + (long long)n0 * ldb;

    float* Cfp = Cf  ? Cf  + zb*sCb + zh*sCh : nullptr;
    bf16*  Chp = Coh ? Coh + zb*sCb + zh*sCh : nullptr;
    bf16*  Clp = Col ? Col + zb*sCb + zh*sCh : nullptr;

#if HAS_TC
    uint32_t sb  = (uint32_t)__cvta_generic_to_shared(dsm);
    uint32_t ctl = sb + (uint32_t)(NST * STAGE);
    uint32_t mb0 = ctl + 8, mb1 = ctl + 16;

    if (tid == 0) { MBARRIER_INIT(mb0, 1); MBARRIER_INIT(mb1, 1); }
    if (wid == 4) { TCGEN05_ALLOC(ctl, TN); TCGEN05_RELINQ(); }
    __syncthreads();
    uint32_t tmem;
    asm volatile("ld.shared.b32 %0, [%1];" : "=r"(tmem) : "r"(ctl));

    const int KT = K >> 6;
    int ph0 = 0, ph1 = 0;

    auto issue = [&](int buf, int k0) {
        const uint32_t sbase = sb + (uint32_t)(buf * STAGE);
        constexpr int ITER = (128 + TN) * 8 / 256;
        #pragma unroll
        for (int i = 0; i < ITER; i++) {
            int id = tid + (i << 8);
            int row = id >> 3, cc = id & 7;
            if (row < 128) {
                uint32_t off = (uint32_t)((row << 7) + (cc << 4));
                uint32_t sw = off ^ ((off >> 3) & 0x70);
                long long ga = (long long)row * lda + k0 + (cc << 3);
                cpa16(sbase + AHOF + sw, Agh + ga, 16);
                cpa16(sbase + ALOF + sw, Agl + ga, 16);
            } else {
                int rb = row - 128;
                uint32_t off = (uint32_t)((rb << 7) + (cc << 4));
                uint32_t sw = off ^ ((off >> 3) & 0x70);
                int sz = 16, br = rb;
                if (rb >= nB) { sz = 0; br = 0; }
                long long gb = (long long)br * ldb + k0 + (cc << 3);
                cpa16(sbase + BHOF + sw, Bgh + gb, sz);
                cpa16(sbase + BLOF + sw, Bgl + gb, sz);
            }
        }
        asm volatile("cp.async.commit_group;");
    };

    auto mma_chunk = [&](int buf, int kt) {
        if (wid == 4) {
            if (elect_one_pred()) {
                const uint32_t sbase = sb + (uint32_t)(buf * STAGE);
                uint64_t dah = MAKE_SMEM_DESC(sbase + AHOF);
                uint64_t dal = MAKE_SMEM_DESC(sbase + ALOF);
                uint64_t dbh = MAKE_SMEM_DESC(sbase + BHOF);
                uint64_t dbl = MAKE_SMEM_DESC(sbase + BLOF);
                #pragma unroll
                for (int s = 0; s < 4; s++) {
                    uint32_t en0 = (kt == 0 && s == 0) ? 0u : 1u;
                    mma_f16_ss(tmem, dah + s*2, dbh + s*2, idesc, en0);
                    mma_f16_ss(tmem, dah + s*2, dbl + s*2, idesc, 1u);
                    mma_f16_ss(tmem, dal + s*2, dbh + s*2, idesc, 1u);
                }
                TCGEN05_COMMIT(buf ? mb1 : mb0);
            }
        }
    };

    issue(0, 0);
    if (NST == 2) {
        for (int kt = 0; kt < KT; kt++) {
            const int buf = kt & 1;
            if (kt + 1 < KT) {
                if (kt >= 1) {
                    if ((buf ^ 1) == 0) { MBARRIER_WAIT_PARITY(mb0, ph0); ph0 ^= 1; }
                    else                { MBARRIER_WAIT_PARITY(mb1, ph1); ph1 ^= 1; }
                }
                issue(buf ^ 1, (kt + 1) << 6);
                asm volatile("cp.async.wait_group 1;");
            } else {
                asm volatile("cp.async.wait_group 0;");
            }
            FENCE_PROXY_ASYNC();
            __syncthreads();
            mma_chunk(buf, kt);
            __syncthreads();
        }
        const int lastbuf = (KT - 1) & 1;
        if (lastbuf == 0) { MBARRIER_WAIT_PARITY(mb0, ph0); }
        else              { MBARRIER_WAIT_PARITY(mb1, ph1); }
    } else {
        for (int kt = 0; kt < KT; kt++) {
            asm volatile("cp.async.wait_group 0;");
            FENCE_PROXY_ASYNC();
            __syncthreads();
            mma_chunk(0, kt);
            __syncthreads();
            if (kt + 1 < KT) {
                MBARRIER_WAIT_PARITY(mb0, ph0); ph0 ^= 1;
                issue(0, (kt + 1) << 6);
            }
        }
        MBARRIER_WAIT_PARITY(mb0, ph0);
    }
    TCGEN05_FENCE_AFTER();

    // epilogue: TMEM -> SMEM pivot -> coalesced stores
    float* stg = (float*)dsm;
    for (int cb = 0; cb < nB; cb += 32) {
        if (wid < 4) {
            uint32_t d[32];
            TCGEN05_LD_32X32B_X32(d, tmem + cb);
            TCGEN05_WAIT_LD();
            int row = (wid << 5) + lane;
            #pragma unroll
            for (int j = 0; j < 32; j++) stg[row * 33 + j] = __uint_as_float(d[j]);
        }
        __syncthreads();
        #pragma unroll
        for (int it = 0; it < 4; it++) {
            int row = (it << 5) + (tid >> 3);
            int cc = (tid & 7) << 2;
            int gc = n0 + cb + cc;
            long long o = (long long)(m0 + row) * ldc + gc;
            float v[4];
            float4 rv;
            if (EPI == 7) rv = *(const float4*)(resid + o);
            #pragma unroll
            for (int j = 0; j < 4; j++) {
                v[j] = stg[row * 33 + cc + j];
                if (EPI == 1 || EPI == 2 || EPI == 4 || EPI == 7) v[j] += bias[gc + j];
                if (EPI == 7) v[j] += ((const float*)&rv)[j];
                if (EPI == 4) v[j] = 0.5f * v[j] * (1.0f + erff(v[j] * 0.70710678118654752f));
            }
            if (EPI <= 1 || EPI == 7) {
                *(float4*)(Cfp + o) = make_float4(v[0], v[1], v[2], v[3]);
            } else {
                bf16 h[4], l[4];
                #pragma unroll
                for (int j = 0; j < 4; j++) split2(v[j], h[j], l[j]);
                ((__nv_bfloat162*)(Chp + o))[0] = __nv_bfloat162(h[0], h[1]);
                ((__nv_bfloat162*)(Chp + o))[1] = __nv_bfloat162(h[2], h[3]);
                ((__nv_bfloat162*)(Clp + o))[0] = __nv_bfloat162(l[0], l[1]);
                ((__nv_bfloat162*)(Clp + o))[1] = __nv_bfloat162(l[2], l[3]);
            }
        }
        __syncthreads();
    }

    TCGEN05_FENCE_BEFORE();
    __syncthreads();
    if (tid == 0) { MBARRIER_INVAL(mb0); MBARRIER_INVAL(mb1); }
    if (wid == 4) TCGEN05_DEALLOC(tmem, TN);
#else
    // trivially-correct scalar fallback (never selected on sm_103a hardware)
    for (int o = tid; o < 128 * TN; o += 256) {
        int m = o / TN, n = o % TN;
        if (n >= nB) continue;
        float s = 0.f;
        const bf16* arh = Agh + (long long)m * lda;
        const bf16* arl = Agl + (long long)m * lda;
        const bf16* brh = Bgh + (long long)n * ldb;
        const bf16* brl = Bgl + (long long)n * ldb;
        for (int k = 0; k < K; k++)
            s += (__bfloat162float(arh[k]) + __bfloat162float(arl[k])) *
                 (__bfloat162float(brh[k]) + __bfloat162float(brl[k]));
        int gc = n0 + n;
        long long off = (long long)(m0 + m) * ldc + gc;
        if (EPI == 1 || EPI == 2 || EPI == 4 || EPI == 7) s += bias[gc];
        if (EPI == 7) s += resid[off];
        if (EPI == 4) s = 0.5f * s * (1.0f + erff(s * 0.70710678118654752f));
        if (EPI <= 1 || EPI == 7) Cfp[off] = s;
        else split2(s, Chp[off], Clp[off]);
    }
#endif
}

// ---------------- fp32 -> bf16 hi/lo split ----------------
__global__ void conv_pair(const float4* __restrict__ src, bf16* __restrict__ h,
                          bf16* __restrict__ l, int n4)
{
    int i = blockIdx.x * 256 + threadIdx.x;
    if (i < n4) {
        float4 v = src[i];
        int b = i * 4;
        split2(v.x, h[b], l[b]);
        split2(v.y, h[b + 1], l[b + 1]);
        split2(v.z, h[b + 2], l[b + 2]);
        split2(v.w, h[b + 3], l[b + 3]);
    }
}

// ---------------- gather concat bias ----------------
__global__ void gather_bias(const float* __restrict__ bq, const float* __restrict__ bk,
                            const float* __restrict__ bc, const float* __restrict__ bv,
                            float* __restrict__ bcat)
{
    int i = blockIdx.x * 256 + threadIdx.x;
    int layer = i / (4 * ND), r = i % (4 * ND);
    int sect = r / ND, c = r % ND;
    const float* s = (sect == 0) ? bq : (sect == 1) ? bk : (sect == 2) ? bc : bv;
    bcat[i] = s[layer * ND + c];
}

// ---------------- transpose + split ----------------
__global__ void transpose_split(const float* __restrict__ src, long long sS,
                                bf16* __restrict__ dh, bf16* __restrict__ dl, long long sD,
                                int R, int C, int lds, int ldd)
{
    __shared__ float t[32][33];
    const float* s = src + (long long)blockIdx.z * sS;
    bf16* oh = dh + (long long)blockIdx.z * sD;
    bf16* ol = dl + (long long)blockIdx.z * sD;
    int r0 = blockIdx.y * 32, c0 = blockIdx.x * 32;
    int tx = threadIdx.x, ty = threadIdx.y;
    #pragma unroll
    for (int i = 0; i < 4; i++) {
        int r = r0 + ty + i * 8;
        if (r < R && c0 + tx < C) t[ty + i * 8][tx] = s[(long long)r * lds + c0 + tx];
    }
    __syncthreads();
    #pragma unroll
    for (int i = 0; i < 4; i++) {
        int c = c0 + ty + i * 8, r = r0 + tx;
        if (c < C && r < R) {
            long long o = (long long)c * ldd + r;
            split2(t[tx][ty + i * 8], oh[o], ol[o]);
        }
    }
}

// ---------------- 4-weight batched transpose for WCAT ----------------
__global__ void transpose_split4(const float* __restrict__ s0, const float* __restrict__ s1,
                                 const float* __restrict__ s2, const float* __restrict__ s3,
                                 bf16* __restrict__ dh, bf16* __restrict__ dl)
{
    __shared__ float t[32][33];
    int widx = blockIdx.z / NL, layer = blockIdx.z % NL;
    const float* s = ((widx == 0) ? s0 : (widx == 1) ? s1 : (widx == 2) ? s2 : s3)
                     + (long long)layer * WDD;
    bf16* oh = dh + (long long)layer * CATW + (long long)widx * WDD;
    bf16* ol = dl + (long long)layer * CATW + (long long)widx * WDD;
    int r0 = blockIdx.y * 32, c0 = blockIdx.x * 32;
    int tx = threadIdx.x, ty = threadIdx.y;
    #pragma unroll
    for (int i = 0; i < 4; i++) {
        int r = r0 + ty + i * 8;
        t[ty + i * 8][tx] = s[(long long)r * 768 + c0 + tx];
    }
    __syncthreads();
    #pragma unroll
    for (int i = 0; i < 4; i++) {
        int c = c0 + ty + i * 8, r = r0 + tx;
        long long o = (long long)c * 768 + r;
        split2(t[tx][ty + i * 8], oh[o], ol[o]);
    }
}

// ---------------- pair transpose ----------------
__global__ void transpose_pair(const bf16* __restrict__ sh, const bf16* __restrict__ sl,
                               long long sSb, long long sSh, int Hdiv,
                               bf16* __restrict__ dh, bf16* __restrict__ dl, long long sD,
                               int R, int C, int lds, int ldd)
{
    __shared__ uint32_t t[32][33];
    int zb = blockIdx.z / Hdiv, zh = blockIdx.z % Hdiv;
    long long so = zb * sSb + zh * sSh;
    bf16* oh = dh + (long long)blockIdx.z * sD;
    bf16* ol = dl + (long long)blockIdx.z * sD;
    int r0 = blockIdx.y * 32, c0 = blockIdx.x * 32;
    int tx = threadIdx.x, ty = threadIdx.y;
    #pragma unroll
    for (int i = 0; i < 4; i++) {
        int r = r0 + ty + i * 8;
        if (r < R && c0 + tx < C) {
            long long a = so + (long long)r * lds + c0 + tx;
            uint16_t hv = __bfloat16_as_ushort(sh[a]);
            uint16_t lv = __bfloat16_as_ushort(sl[a]);
            t[ty + i * 8][tx] = (uint32_t)hv | ((uint32_t)lv << 16);
        }
    }
    __syncthreads();
    #pragma unroll
    for (int i = 0; i < 4; i++) {
        int c = c0 + ty + i * 8, r = r0 + tx;
        if (c < C && r < R) {
            long long o = (long long)c * ldd + r;
            uint32_t v = t[tx][ty + i * 8];
            oh[o] = __ushort_as_bfloat16((uint16_t)(v & 0xffff));
            ol[o] = __ushort_as_bfloat16((uint16_t)(v >> 16));
        }
    }
}

// ---------------- diag -> 1/||c|| ----------------
__global__ void diag_rsqrt_kernel(const float* __restrict__ Gc, float* __restrict__ cninv)
{
    int i = blockIdx.x * 256 + threadIdx.x;
    if (i < NBH * NS) {
        int bh = i / NS, s = i % NS;
        cninv[i] = rsqrtf(Gc[((long long)bh * NS + s) * NS + s]);
    }
}

// ---------------- blend + dual softmax: 1 warp per row ----------------
__global__ __launch_bounds__(256) void blend_softmax2(
    const float* __restrict__ Gc, const float* __restrict__ Gqk,
    const float* __restrict__ cninv, bf16* __restrict__ ph, bf16* __restrict__ pl)
{
    const int lane = threadIdx.x & 31, wid = threadIdx.x >> 5;
    const int row = blockIdx.x * 8 + wid;
    const int bh = blockIdx.y;
    const long long base = ((long long)bh * NS + row) * NS;
    const float4* gc4 = (const float4*)(Gc + base);
    const float4* gq4 = (const float4*)(Gqk + base);
    const float4* cn4 = (const float4*)(cninv + bh * NS);
    const float cl = cninv[bh * NS + row];

    float s1[16], s2[16];
    #pragma unroll
    for (int j = 0; j < 4; j++) {
        int idx = j * 32 + lane;
        float4 g = gc4[idx];
        float4 q = gq4[idx];
        float4 cr = cn4[idx];
        int c0 = idx * 4;
        s1[j*4+0] = 1.0f - g.x * cl * cr.x + (c0     == row ? 1.0f : 0.0f);
        s1[j*4+1] = 1.0f - g.y * cl * cr.y + (c0 + 1 == row ? 1.0f : 0.0f);
        s1[j*4+2] = 1.0f - g.z * cl * cr.z + (c0 + 2 == row ? 1.0f : 0.0f);
        s1[j*4+3] = 1.0f - g.w * cl * cr.w + (c0 + 3 == row ? 1.0f : 0.0f);
        s2[j*4+0] = q.x * 0.125f;
        s2[j*4+1] = q.y * 0.125f;
        s2[j*4+2] = q.z * 0.125f;
        s2[j*4+3] = q.w * 0.125f;
    }
    float m1 = -1e30f, m2 = -1e30f;
    #pragma unroll
    for (int j = 0; j < 16; j++) { m1 = fmaxf(m1, s1[j]); m2 = fmaxf(m2, s2[j]); }
    #pragma unroll
    for (int o = 16; o; o >>= 1) {
        m1 = fmaxf(m1, __shfl_xor_sync(0xffffffffu, m1, o));
        m2 = fmaxf(m2, __shfl_xor_sync(0xffffffffu, m2, o));
    }
    float sum1 = 0.f, sum2 = 0.f;
    #pragma unroll
    for (int j = 0; j < 16; j++) {
        s1[j] = __expf(s1[j] - m1); sum1 += s1[j];
        s2[j] = __expf(s2[j] - m2); sum2 += s2[j];
    }
    #pragma unroll
    for (int o = 16; o; o >>= 1) {
        sum1 += __shfl_xor_sync(0xffffffffu, sum1, o);
        sum2 += __shfl_xor_sync(0xffffffffu, sum2, o);
    }
    float inv1 = 0.5f / sum1, inv2 = 0.5f / sum2;
    #pragma unroll
    for (int j = 0; j < 4; j++) {
        int c0 = (j * 32 + lane) * 4;
        __nv_bfloat162 h2[2], l2[2];
        #pragma unroll
        for (int e = 0; e < 4; e++) {
            float p = s1[j*4+e] * inv1 + s2[j*4+e] * inv2;
            bf16 h, l;
            split2(p, h, l);
            ((bf16*)h2)[e] = h;
            ((bf16*)l2)[e] = l;
        }
        *(uint2*)(ph + base + c0) = *(uint2*)h2;
        *(uint2*)(pl + base + c0) = *(uint2*)l2;
    }
}

// ---------------- LayerNorm, warp-per-row ----------------
__global__ __launch_bounds__(256) void ln_warp(
    const float* __restrict__ inp,
    const float* __restrict__ g, const float* __restrict__ b,
    float* __restrict__ outf, bf16* __restrict__ outh, bf16* __restrict__ outl)
{
    const int lane = threadIdx.x & 31, wid = threadIdx.x >> 5;
    const long long row = (long long)blockIdx.x * 8 + wid;
    const float4* ip4 = (const float4*)(inp + row * ND);

    float4 v[6];
    float s = 0.f;
    #pragma unroll
    for (int j = 0; j < 6; j++) {
        v[j] = ip4[j * 32 + lane];
        s += v[j].x + v[j].y + v[j].z + v[j].w;
    }
    #pragma unroll
    for (int o = 16; o; o >>= 1) s += __shfl_xor_sync(0xffffffffu, s, o);
    const float mu = s * (1.0f / ND);

    float q = 0.f;
    #pragma unroll
    for (int j = 0; j < 6; j++) {
        float a0 = v[j].x - mu, a1 = v[j].y - mu, a2 = v[j].z - mu, a3 = v[j].w - mu;
        q += a0*a0 + a1*a1 + a2*a2 + a3*a3;
    }
    #pragma unroll
    for (int o = 16; o; o >>= 1) q += __shfl_xor_sync(0xffffffffu, q, o);
    const float inv = rsqrtf(q * (1.0f / ND) + 1e-12f);

    #pragma unroll
    for (int j = 0; j < 6; j++) {
        int c = (j * 32 + lane) * 4;
        long long o = row * ND + c;
        float4 gg = *(const float4*)(g + c);
        float4 bb = *(const float4*)(b + c);
        float r0 = (v[j].x - mu) * inv * gg.x + bb.x;
        float r1 = (v[j].y - mu) * inv * gg.y + bb.y;
        float r2 = (v[j].z - mu) * inv * gg.z + bb.z;
        float r3 = (v[j].w - mu) * inv * gg.w + bb.w;
        *(float4*)(outf + o) = make_float4(r0, r1, r2, r3);
        __nv_bfloat162 h2[2], l2[2];
        bf16 h, l;
        split2(r0, h, l); h2[0].x = h; l2[0].x = l;
        split2(r1, h, l); h2[0].y = h; l2[0].y = l;
        split2(r2, h, l); h2[1].x = h; l2[1].x = l;
        split2(r3, h, l); h2[1].y = h; l2[1].y = l;
        *(uint2*)(outh + o) = *(uint2*)h2;
        *(uint2*)(outl + o) = *(uint2*)l2;
    }
}

// ---------------- host ----------------
static float* symf(const void* s) { void* p = nullptr; cudaGetSymbolAddress(&p, s); return (float*)p; }
static bf16*  symb(const void* s) { void* p = nullptr; cudaGetSymbolAddress(&p, s); return (bf16*)p; }

#define SMEMSZ(TN, nst) ((nst) * ((128 + (TN)) * 256) + 64)

extern "C" void kernel_launch(void* const* d_in, const int* in_sizes, int n_in,
                              void* d_out, int out_size)
{
    const float* hs  = (const float*)d_in[0];
    const float* Wq  = (const float*)d_in[1];  const float* bq  = (const float*)d_in[2];
    const float* Wk  = (const float*)d_in[3];  const float* bk  = (const float*)d_in[4];
    const float* Wv  = (const float*)d_in[5];  const float* bv  = (const float*)d_in[6];
    const float* Wc  = (const float*)d_in[7];  const float* bc  = (const float*)d_in[8];
    const float* Wo  = (const float*)d_in[9];  const float* bo  = (const float*)d_in[10];
    const float* g1  = (const float*)d_in[11]; const float* b1  = (const float*)d_in[12];
    const float* Wi  = (const float*)d_in[13]; const float* bi  = (const float*)d_in[14];
    const float* Wo2 = (const float*)d_in[15]; const float* bo2 = (const float*)d_in[16];
    const float* g2  = (const float*)d_in[17]; const float* b2  = (const float*)d_in[18];

    const int SM256_1 = SMEMSZ(256, 1);   // 98368  -> 2 CTAs/SM
    const int SM128_1 = SMEMSZ(128, 1);   // 65600  -> 3 CTAs/SM
    const int SM64_2  = SMEMSZ(64, 2);    // 98368  -> 2 CTAs/SM

    cudaFuncSetAttribute(gemm_tc<0, 256, 1>, cudaFuncAttributeMaxDynamicSharedMemorySize, SM256_1);
    cudaFuncSetAttribute(gemm_tc<2, 128, 1>, cudaFuncAttributeMaxDynamicSharedMemorySize, SM128_1);
    cudaFuncSetAttribute(gemm_tc<4, 128, 1>, cudaFuncAttributeMaxDynamicSharedMemorySize, SM128_1);
    cudaFuncSetAttribute(gemm_tc<7, 128, 1>, cudaFuncAttributeMaxDynamicSharedMemorySize, SM128_1);
    cudaFuncSetAttribute(gemm_tc<3, 64, 2>,  cudaFuncAttributeMaxDynamicSharedMemorySize, SM64_2);

    float* XF   = symf(g_xf);
    float* TMP  = symf(g_tmp);
    float* ATTF = symf(g_attnf);
    float* S1   = symf(g_s1);
    float* S2   = symf(g_s2);
    float* CN   = symf(g_cninv);
    float* BCAT = symf(g_bcat);

    bf16 *XH = symb(g_xh), *XL = symb(g_xl);
    bf16 *PRJH = symb(g_prjh), *PRJL = symb(g_prjl);
    bf16 *CXH = symb(g_ctxh), *CXL = symb(g_ctxl);
    bf16 *ATH = symb(g_ath), *ATL = symb(g_atl);
    bf16 *HH = symb(g_hh), *HL = symb(g_hl);
    bf16 *PH = symb(g_ph), *PL = symb(g_pl);
    bf16 *VTH = symb(g_vth), *VTL = symb(g_vtl);

    bf16 *WCATH = symb(g_wcath), *WCATL = symb(g_wcatl);
    bf16 *WOH = symb(g_woh), *WOL = symb(g_wol);
    bf16 *WIH = symb(g_wih), *WIL = symb(g_wil);
    bf16 *WO2H = symb(g_wo2h), *WO2L = symb(g_wo2l);

    const long long SD   = (long long)NS * ND;
    const long long SDP  = (long long)NS * (4 * ND);
    const long long SS   = (long long)NS * NS;
    const long long HSS  = (long long)NH * SS;
    const long long VTS  = (long long)NDH * NS;

    const uint32_t ID256 = 0x8000490u | (32u << 17);
    const uint32_t ID128 = 0x8000490u | (16u << 17);
    const uint32_t ID64  = 0x8000490u | (8u << 17);

    dim3 tb(32, 8);

    conv_pair<<<(MROWS * ND / 4 + 255) / 256, 256>>>((const float4*)hs, XH, XL, MROWS * ND / 4);
    gather_bias<<<(NL * 4 * ND) / 256, 256>>>(bq, bk, bc, bv, BCAT);
    transpose_split4<<<dim3(24, 24, 4 * NL), tb>>>(Wq, Wk, Wc, Wv, WCATH, WCATL);
    cudaMemcpyAsync(XF, hs, sizeof(float) * MROWS * ND, cudaMemcpyDeviceToDevice);

    bool late_t = false;
    for (int i = 0; i < NL; i++) {
        const size_t oDD = (size_t)i * WDD, oDF = (size_t)i * WDF, oCAT = (size_t)i * CATW;

        // fused q|k|c|v projection (TN=128, 1-stage, 3 CTAs/SM)
        gemm_tc<2, 128, 1><<<dim3(24, 64, 1), 256, SM128_1>>>(
            XH, XL, 768, 0, 0, WCATH + oCAT, WCATL + oCAT, 768, 0, 0,
            nullptr, PRJH, PRJL, 3072, 0, 0, BCAT + i*4*ND, 3072, 768, 1, ID128, nullptr);

        // V^T per head
        transpose_pair<<<dim3(2, 16, NBH), tb>>>(PRJH + 3*ND, PRJL + 3*ND, SDP, NDH, NH,
                                                 VTH, VTL, VTS, 512, 64, 4*ND, 512);

        // score gram GEMMs (TN=256, 1-stage, KT==1, 2 CTAs/SM) — launch #5 for ncu
        dim3 gS(2, 4, NBH);
        gemm_tc<0, 256, 1><<<gS, 256, SM256_1>>>(
            PRJH + 2*ND, PRJL + 2*ND, 4*ND, SDP, NDH,
            PRJH + 2*ND, PRJL + 2*ND, 4*ND, SDP, NDH,
            S1, nullptr, nullptr, 512, HSS, SS, nullptr, 512, 64, NH, ID256, nullptr);
        gemm_tc<0, 256, 1><<<gS, 256, SM256_1>>>(
            PRJH + 0*ND, PRJL + 0*ND, 4*ND, SDP, NDH,
            PRJH + 1*ND, PRJL + 1*ND, 4*ND, SDP, NDH,
            S2, nullptr, nullptr, 512, HSS, SS, nullptr, 512, 64, NH, ID256, nullptr);

        if (!late_t) {
            transpose_split<<<dim3(24, 24, NL), tb>>>(Wo,  WDD, WOH,  WOL,  WDD, 768, 768, 768, 768);
            transpose_split<<<dim3(96, 24, NL), tb>>>(Wi,  WDF, WIH,  WIL,  WDF, 768, 3072, 3072, 768);
            transpose_split<<<dim3(24, 96, NL), tb>>>(Wo2, WDF, WO2H, WO2L, WDF, 3072, 768, 768, 3072);
            late_t = true;
        }

        diag_rsqrt_kernel<<<(NBH * NS + 255) / 256, 256>>>(S1, CN);
        blend_softmax2<<<dim3(NS/8, NBH), 256>>>(S1, S2, CN, PH, PL);

        // ctx = P @ V^T (2-stage TN=64, proven)
        gemm_tc<3, 64, 2><<<dim3(1, 4, NBH), 256, SM64_2>>>(
            PH, PL, 512, HSS, SS, VTH, VTL, 512, (long long)NH * VTS, VTS,
            nullptr, CXH, CXL, 768, SD, NDH, nullptr, 64, 512, NH, ID64, nullptr);

        // TMP = ctx @ Wo + bo + x (TN=128, 1-stage, 3 CTAs/SM); then LN
        gemm_tc<7, 128, 1><<<dim3(6, 64, 1), 256, SM128_1>>>(
            CXH, CXL, 768, 0, 0, WOH + oDD, WOL + oDD, 768, 0, 0,
            TMP, nullptr, nullptr, 768, 0, 0, bo + i * ND, 768, 768, 1, ID128, XF);
        ln_warp<<<MROWS / 8, 256>>>(TMP, g1 + i * ND, b1 + i * ND, ATTF, ATH, ATL);

        // h = gelu(attn @ Wi + bi) (TN=128, 1-stage, 3 CTAs/SM)
        gemm_tc<4, 128, 1><<<dim3(24, 64, 1), 256, SM128_1>>>(
            ATH, ATL, 768, 0, 0, WIH + oDF, WIL + oDF, 768, 0, 0,
            nullptr, HH, HL, 3072, 0, 0, bi + i * NF, 3072, 768, 1, ID128, nullptr);

        // TMP = h @ Wo2 + bo2 + attn (TN=128, 1-stage); then LN -> x
        gemm_tc<7, 128, 1><<<dim3(6, 64, 1), 256, SM128_1>>>(
            HH, HL, 3072, 0, 0, WO2H + oDF, WO2L + oDF, 3072, 0, 0,
            TMP, nullptr, nullptr, 768, 0, 0, bo2 + i * ND, 768, 3072, 1, ID128, ATTF);
        ln_warp<<<MROWS / 8, 256>>>(TMP, g2 + i * ND, b2 + i * ND, XF, XH, XL);
    }

    cudaMemcpyAsync(d_out, XF, sizeof(float) * MROWS * ND, cudaMemcpyDeviceToDevice);
}